// round 7
// baseline (speedup 1.0000x reference)
#include <cuda_runtime.h>
#include <cuda_fp16.h>
#include <math_constants.h>

#define NN   20000
#define EE   320000
#define RT   512
#define HC   256      // H*C

// ---------------- scratch (device globals: allocation-free) ----------------
__device__ float   g_xl[NN * HC];
__device__ float   g_xr[NN * HC];
__device__ __half2 g_reh[RT * 128];   // relations @ We^T, fp16 (128 half2 per row)
__device__ float   g_h1[NN * 64];     // layer-0 output
__device__ int     g_deg[NN];
__device__ int     g_rowptr[NN + 1];
__device__ int     g_cursor[NN];
__device__ int     g_csr[EE];
__device__ int2    g_srcrel[EE];      // (src, rel) per sorted CSR slot

// ---------------- CSR build ----------------
__global__ void k_count(const int* __restrict__ ei) {
    int i = blockIdx.x * blockDim.x + threadIdx.x;
    if (i < EE) atomicAdd(&g_deg[ei[EE + i]], 1);
}

__global__ void k_scan() {
    __shared__ int wsum[32];
    __shared__ int carry;
    int tid = threadIdx.x, lane = tid & 31, wid = tid >> 5;
    if (tid == 0) { carry = 0; g_rowptr[0] = 0; }
    __syncthreads();
    for (int base = 0; base < NN; base += 1024) {
        int i = base + tid;
        int x = (i < NN) ? g_deg[i] : 0;
#pragma unroll
        for (int off = 1; off < 32; off <<= 1) {
            int t = __shfl_up_sync(0xffffffffu, x, off);
            if (lane >= off) x += t;
        }
        if (lane == 31) wsum[wid] = x;
        __syncthreads();
        if (wid == 0) {
            int s = wsum[lane];
#pragma unroll
            for (int off = 1; off < 32; off <<= 1) {
                int t = __shfl_up_sync(0xffffffffu, s, off);
                if (lane >= off) s += t;
            }
            wsum[lane] = s;
        }
        __syncthreads();
        int total = wsum[31];
        int prefix = carry + (wid ? wsum[wid - 1] : 0) + x;
        if (i < NN) g_rowptr[i + 1] = prefix;
        __syncthreads();
        if (tid == 0) carry += total;
        __syncthreads();
    }
}

__global__ void k_scatter(const int* __restrict__ ei) {
    int i = blockIdx.x * blockDim.x + threadIdx.x;
    if (i >= EE) return;
    int d = ei[EE + i];
    int pos = atomicAdd(&g_cursor[d], 1);
    g_csr[g_rowptr[d] + pos] = i;
}

// sort each segment by edge id (local buf) and emit (src, rel) directly
__global__ void k_sortpack(const int* __restrict__ ei, const int* __restrict__ relidx) {
    int n = blockIdx.x * blockDim.x + threadIdx.x;
    if (n >= NN) return;
    int beg = g_rowptr[n], end = g_rowptr[n + 1];
    int len = end - beg;
    if (len <= 128) {
        int buf[128];
        for (int i = 0; i < len; i++) buf[i] = g_csr[beg + i];
        for (int i = 1; i < len; i++) {
            int v = buf[i];
            int j = i - 1;
            while (j >= 0 && buf[j] > v) { buf[j + 1] = buf[j]; j--; }
            buf[j + 1] = v;
        }
        for (int i = 0; i < len; i++) {
            int e = buf[i];
            g_srcrel[beg + i] = make_int2(ei[e], relidx[e]);
        }
    } else {
        for (int i = beg + 1; i < end; i++) {
            int v = g_csr[i];
            int j = i - 1;
            while (j >= beg && g_csr[j] > v) { g_csr[j + 1] = g_csr[j]; j--; }
            g_csr[j + 1] = v;
        }
        for (int i = beg; i < end; i++) {
            int e = g_csr[i];
            g_srcrel[i] = make_int2(ei[e], relidx[e]);
        }
    }
}

// ---------------- tf32 helpers ----------------
__device__ __forceinline__ unsigned f2tf32(float f) {
    unsigned u;
    asm("cvt.rna.tf32.f32 %0, %1;" : "=r"(u) : "f"(f));
    return u;
}
__device__ __forceinline__ void mma_tf32(float& c0, float& c1, float& c2, float& c3,
                                         unsigned a0, unsigned a1, unsigned a2, unsigned a3,
                                         unsigned b0, unsigned b1) {
    asm("mma.sync.aligned.m16n8k8.row.col.f32.tf32.tf32.f32 "
        "{%0,%1,%2,%3},{%4,%5,%6,%7},{%8,%9},{%0,%1,%2,%3};"
        : "+f"(c0), "+f"(c1), "+f"(c2), "+f"(c3)
        : "r"(a0), "r"(a1), "r"(a2), "r"(a3), "r"(b0), "r"(b1));
}

// ---- tensor-core GEMM: out[M,256] = A[M,64] @ W[256,64]^T + bias ----
__global__ __launch_bounds__(256) void k_gemm_tc(const float* __restrict__ A,
                                                 const float* __restrict__ W0,
                                                 const float* __restrict__ bias0,
                                                 float* __restrict__ out0,
                                                 const float* __restrict__ W1,
                                                 const float* __restrict__ bias1,
                                                 float* __restrict__ out1, int M) {
    const float* W    = blockIdx.z ? W1 : W0;
    const float* bias = blockIdx.z ? bias1 : bias0;
    float* out        = blockIdx.z ? out1 : out0;
    __shared__ unsigned As[64][68];
    __shared__ unsigned Ws[64][68];
    int tid = threadIdx.x;
    int row0 = blockIdx.x * 64, n0 = blockIdx.y * 64;

#pragma unroll
    for (int it = 0; it < 4; it++) {
        int idx = tid + it * 256;
        int r = idx >> 4, k4 = idx & 15;
        int m = row0 + r;
        float4 v = (m < M) ? *(const float4*)(A + (size_t)m * 64 + k4 * 4)
                           : make_float4(0.f, 0.f, 0.f, 0.f);
        As[r][k4 * 4 + 0] = f2tf32(v.x); As[r][k4 * 4 + 1] = f2tf32(v.y);
        As[r][k4 * 4 + 2] = f2tf32(v.z); As[r][k4 * 4 + 3] = f2tf32(v.w);
        float4 wv = *(const float4*)(W + (size_t)(n0 + r) * 64 + k4 * 4);
        Ws[r][k4 * 4 + 0] = f2tf32(wv.x); Ws[r][k4 * 4 + 1] = f2tf32(wv.y);
        Ws[r][k4 * 4 + 2] = f2tf32(wv.z); Ws[r][k4 * 4 + 3] = f2tf32(wv.w);
    }
    __syncthreads();

    int wid = tid >> 5, lane = tid & 31;
    int g = lane >> 2, tig = lane & 3;
    int rbase = (wid & 3) * 16;
    int ncb = (wid >> 2) * 32;
    float acc[4][4] = {};
#pragma unroll
    for (int ks = 0; ks < 8; ks++) {
        int k0 = ks * 8;
        unsigned a0 = As[rbase + g][k0 + tig];
        unsigned a1 = As[rbase + g + 8][k0 + tig];
        unsigned a2 = As[rbase + g][k0 + tig + 4];
        unsigned a3 = As[rbase + g + 8][k0 + tig + 4];
#pragma unroll
        for (int nt = 0; nt < 4; nt++) {
            unsigned b0 = Ws[ncb + nt * 8 + g][k0 + tig];
            unsigned b1 = Ws[ncb + nt * 8 + g][k0 + tig + 4];
            mma_tf32(acc[nt][0], acc[nt][1], acc[nt][2], acc[nt][3],
                     a0, a1, a2, a3, b0, b1);
        }
    }
    int m0 = row0 + rbase + g;
#pragma unroll
    for (int nt = 0; nt < 4; nt++) {
        int gcol = n0 + ncb + nt * 8 + tig * 2;
        float2 bv = *(const float2*)(bias + gcol);
        if (m0 < M)
            *(float2*)(out + (size_t)m0 * 256 + gcol) =
                make_float2(acc[nt][0] + bv.x, acc[nt][1] + bv.y);
        if (m0 + 8 < M)
            *(float2*)(out + (size_t)(m0 + 8) * 256 + gcol) =
                make_float2(acc[nt][2] + bv.x, acc[nt][3] + bv.y);
    }
}

// ---- scalar fp32 GEMM -> fp16 output (relations @ We^T) ----
__global__ __launch_bounds__(256) void k_gemm_re(const float* __restrict__ A,
                                                 const float* __restrict__ W,
                                                 __half2* __restrict__ out, int M) {
    __shared__ float xsT[32][132];
    __shared__ float Ws[32][68];
    int tid = threadIdx.x;
    int row0 = blockIdx.x * 128, n0 = blockIdx.y * 64;
    int rg = tid >> 4, cg = tid & 15;
    int r0 = rg * 8, c0 = cg * 4;
    float acc[8][4] = {};

    for (int kc = 0; kc < 64; kc += 32) {
#pragma unroll
        for (int it = 0; it < 4; ++it) {
            int idx = tid + it * 256;
            int r = idx >> 3, k4 = idx & 7;
            int m = row0 + r;
            float4 v = (m < M) ? *(const float4*)(A + (size_t)m * 64 + kc + k4 * 4)
                               : make_float4(0.f, 0.f, 0.f, 0.f);
            xsT[k4 * 4 + 0][r] = v.x; xsT[k4 * 4 + 1][r] = v.y;
            xsT[k4 * 4 + 2][r] = v.z; xsT[k4 * 4 + 3][r] = v.w;
        }
#pragma unroll
        for (int it = 0; it < 2; ++it) {
            int idx = tid + it * 256;
            int n = idx >> 3, k4 = idx & 7;
            float4 v = *(const float4*)(W + (size_t)(n0 + n) * 64 + kc + k4 * 4);
            Ws[k4 * 4 + 0][n] = v.x; Ws[k4 * 4 + 1][n] = v.y;
            Ws[k4 * 4 + 2][n] = v.z; Ws[k4 * 4 + 3][n] = v.w;
        }
        __syncthreads();
#pragma unroll
        for (int k = 0; k < 32; k++) {
            float4 x0 = *(const float4*)&xsT[k][r0];
            float4 x1 = *(const float4*)&xsT[k][r0 + 4];
            float4 wv = *(const float4*)&Ws[k][c0];
            float xv[8] = {x0.x, x0.y, x0.z, x0.w, x1.x, x1.y, x1.z, x1.w};
#pragma unroll
            for (int r = 0; r < 8; r++) {
                acc[r][0] += xv[r] * wv.x; acc[r][1] += xv[r] * wv.y;
                acc[r][2] += xv[r] * wv.z; acc[r][3] += xv[r] * wv.w;
            }
        }
        __syncthreads();
    }
#pragma unroll
    for (int r = 0; r < 8; r++) {
        int m = row0 + r0 + r;
        if (m < M) {
            __half2 h0 = __floats2half2_rn(acc[r][0], acc[r][1]);
            __half2 h1 = __floats2half2_rn(acc[r][2], acc[r][3]);
            *(uint2*)(out + (size_t)m * 128 + (n0 + c0) / 2) =
                make_uint2(*(unsigned*)&h0, *(unsigned*)&h1);
        }
    }
}

// ---------------- fused alpha + online softmax + aggregation + self-loop ----------
struct Rows { float4 xlA, xlB, eeA, eeB; };

__device__ __forceinline__ float4 h4_to_f4(uint2 u) {
    __half2 h0 = *(__half2*)&u.x, h1 = *(__half2*)&u.y;
    float2 lo = __half22float2(h0), hi = __half22float2(h1);
    return make_float4(lo.x, lo.y, hi.x, hi.y);
}

__device__ __forceinline__ void load_rows(Rows& r, int src, int rel, int lane) {
    const float* xlp = g_xl + (size_t)src * HC;
    const __half2* eep = g_reh + (size_t)rel * 128;
    r.xlA = *(const float4*)(xlp + 4 * lane);
    r.xlB = *(const float4*)(xlp + 128 + 4 * lane);
    r.eeA = h4_to_f4(*(const uint2*)(eep + 2 * lane));
    r.eeB = h4_to_f4(*(const uint2*)(eep + 64 + 2 * lane));
}

__device__ __forceinline__ void logits(const Rows& r, float4 xrA, float4 xrB,
                                       float4 attA, float4 attB,
                                       float& pA, float& pB) {
    float t;
    t = r.xlA.x + xrA.x + r.eeA.x; t = t > 0.f ? t : 0.2f * t; pA  = t * attA.x;
    t = r.xlA.y + xrA.y + r.eeA.y; t = t > 0.f ? t : 0.2f * t; pA += t * attA.y;
    t = r.xlA.z + xrA.z + r.eeA.z; t = t > 0.f ? t : 0.2f * t; pA += t * attA.z;
    t = r.xlA.w + xrA.w + r.eeA.w; t = t > 0.f ? t : 0.2f * t; pA += t * attA.w;
    t = r.xlB.x + xrB.x + r.eeB.x; t = t > 0.f ? t : 0.2f * t; pB  = t * attB.x;
    t = r.xlB.y + xrB.y + r.eeB.y; t = t > 0.f ? t : 0.2f * t; pB += t * attB.y;
    t = r.xlB.z + xrB.z + r.eeB.z; t = t > 0.f ? t : 0.2f * t; pB += t * attB.z;
    t = r.xlB.w + xrB.w + r.eeB.w; t = t > 0.f ? t : 0.2f * t; pB += t * attB.w;
}

__device__ __forceinline__ void online_update(float pA, float pB, const Rows& r,
                                              float& mA, float& mB, float& sA, float& sB,
                                              float4& accA, float4& accB) {
    float nm = fmaxf(mA, pA);
    float scl = __expf(mA - nm);
    float wgt = __expf(pA - nm);
    sA = sA * scl + wgt;
    accA.x = accA.x * scl + wgt * r.xlA.x;
    accA.y = accA.y * scl + wgt * r.xlA.y;
    accA.z = accA.z * scl + wgt * r.xlA.z;
    accA.w = accA.w * scl + wgt * r.xlA.w;
    mA = nm;
    nm = fmaxf(mB, pB);
    scl = __expf(mB - nm);
    wgt = __expf(pB - nm);
    sB = sB * scl + wgt;
    accB.x = accB.x * scl + wgt * r.xlB.x;
    accB.y = accB.y * scl + wgt * r.xlB.y;
    accB.z = accB.z * scl + wgt * r.xlB.z;
    accB.w = accB.w * scl + wgt * r.xlB.w;
    mB = nm;
}

__global__ __launch_bounds__(256) void k_fused(const float* __restrict__ att,
                                               const float* __restrict__ bias,
                                               float* __restrict__ out) {
    int w = (blockIdx.x * blockDim.x + threadIdx.x) >> 5;
    int lane = threadIdx.x & 31;
    if (w >= NN) return;
    int beg = g_rowptr[w], end = g_rowptr[w + 1];

    float4 attA = *(const float4*)(att + ((lane >> 4) * 64) + (lane & 15) * 4);
    float4 attB = *(const float4*)(att + 128 + ((lane >> 4) * 64) + (lane & 15) * 4);

    const float* xrp = g_xr + (size_t)w * HC;
    float4 xrA = *(const float4*)(xrp + 4 * lane);
    float4 xrB = *(const float4*)(xrp + 128 + 4 * lane);

    float mA = -CUDART_INF_F, mB = -CUDART_INF_F;
    float sA = 0.f, sB = 0.f;
    float4 accA = make_float4(0.f, 0.f, 0.f, 0.f);
    float4 accB = make_float4(0.f, 0.f, 0.f, 0.f);
    float4 esA = make_float4(0.f, 0.f, 0.f, 0.f);
    float4 esB = make_float4(0.f, 0.f, 0.f, 0.f);

    int i = beg;
    for (; i + 2 <= end; i += 2) {
        int2 sr0 = g_srcrel[i];
        int2 sr1 = g_srcrel[i + 1];
        Rows r0, r1;
        load_rows(r0, sr0.x, sr0.y, lane);
        load_rows(r1, sr1.x, sr1.y, lane);
        esA.x += r0.eeA.x; esA.y += r0.eeA.y; esA.z += r0.eeA.z; esA.w += r0.eeA.w;
        esB.x += r0.eeB.x; esB.y += r0.eeB.y; esB.z += r0.eeB.z; esB.w += r0.eeB.w;
        esA.x += r1.eeA.x; esA.y += r1.eeA.y; esA.z += r1.eeA.z; esA.w += r1.eeA.w;
        esB.x += r1.eeB.x; esB.y += r1.eeB.y; esB.z += r1.eeB.z; esB.w += r1.eeB.w;

        float p0A, p0B, p1A, p1B;
        logits(r0, xrA, xrB, attA, attB, p0A, p0B);
        logits(r1, xrA, xrB, attA, attB, p1A, p1B);
#pragma unroll
        for (int off = 1; off < 16; off <<= 1) {
            p0A += __shfl_xor_sync(0xffffffffu, p0A, off);
            p0B += __shfl_xor_sync(0xffffffffu, p0B, off);
            p1A += __shfl_xor_sync(0xffffffffu, p1A, off);
            p1B += __shfl_xor_sync(0xffffffffu, p1B, off);
        }
        online_update(p0A, p0B, r0, mA, mB, sA, sB, accA, accB);
        online_update(p1A, p1B, r1, mA, mB, sA, sB, accA, accB);
    }
    if (i < end) {
        int2 sr = g_srcrel[i];
        Rows r;
        load_rows(r, sr.x, sr.y, lane);
        esA.x += r.eeA.x; esA.y += r.eeA.y; esA.z += r.eeA.z; esA.w += r.eeA.w;
        esB.x += r.eeB.x; esB.y += r.eeB.y; esB.z += r.eeB.z; esB.w += r.eeB.w;
        float pA, pB;
        logits(r, xrA, xrB, attA, attB, pA, pB);
#pragma unroll
        for (int off = 1; off < 16; off <<= 1) {
            pA += __shfl_xor_sync(0xffffffffu, pA, off);
            pB += __shfl_xor_sync(0xffffffffu, pB, off);
        }
        online_update(pA, pB, r, mA, mB, sA, sB, accA, accB);
    }

    {   // self-loop: ee = mean of incoming ee rows, xl = xl[w]
        int deg = end - beg;
        float inv = 1.f / (float)(deg > 1 ? deg : 1);
        Rows r;
        r.eeA = make_float4(esA.x * inv, esA.y * inv, esA.z * inv, esA.w * inv);
        r.eeB = make_float4(esB.x * inv, esB.y * inv, esB.z * inv, esB.w * inv);
        const float* xlp = g_xl + (size_t)w * HC;
        r.xlA = *(const float4*)(xlp + 4 * lane);
        r.xlB = *(const float4*)(xlp + 128 + 4 * lane);
        float pA, pB;
        logits(r, xrA, xrB, attA, attB, pA, pB);
#pragma unroll
        for (int off = 1; off < 16; off <<= 1) {
            pA += __shfl_xor_sync(0xffffffffu, pA, off);
            pB += __shfl_xor_sync(0xffffffffu, pB, off);
        }
        online_update(pA, pB, r, mA, mB, sA, sB, accA, accB);
    }

    float iA = 1.f / sA, iB = 1.f / sB;
    accA.x *= iA; accA.y *= iA; accA.z *= iA; accA.w *= iA;
    accB.x *= iB; accB.y *= iB; accB.z *= iB; accB.w *= iB;
    accA.x += __shfl_xor_sync(0xffffffffu, accA.x, 16);
    accA.y += __shfl_xor_sync(0xffffffffu, accA.y, 16);
    accA.z += __shfl_xor_sync(0xffffffffu, accA.z, 16);
    accA.w += __shfl_xor_sync(0xffffffffu, accA.w, 16);
    accB.x += __shfl_xor_sync(0xffffffffu, accB.x, 16);
    accB.y += __shfl_xor_sync(0xffffffffu, accB.y, 16);
    accB.z += __shfl_xor_sync(0xffffffffu, accB.z, 16);
    accB.w += __shfl_xor_sync(0xffffffffu, accB.w, 16);
    if (lane < 16) {
        float4 bv = *(const float4*)(bias + 4 * lane);
        float4 o;
        o.x = 0.25f * (accA.x + accB.x) + bv.x;
        o.y = 0.25f * (accA.y + accB.y) + bv.y;
        o.z = 0.25f * (accA.z + accB.z) + bv.z;
        o.w = 0.25f * (accA.w + accB.w) + bv.w;
        *(float4*)(out + (size_t)w * 64 + 4 * lane) = o;
    }
}

// ---------------- host ----------------
extern "C" void kernel_launch(void* const* d_in, const int* in_sizes, int n_in,
                              void* d_out, int out_size) {
    const float* x         = (const float*)d_in[0];
    const int* ei          = (const int*)d_in[1];
    const float* relations = (const float*)d_in[2];
    const int* relidx      = (const int*)d_in[3];
    const float* Wl[2]  = {(const float*)d_in[4],  (const float*)d_in[11]};
    const float* blv[2] = {(const float*)d_in[5],  (const float*)d_in[12]};
    const float* Wr[2]  = {(const float*)d_in[6],  (const float*)d_in[13]};
    const float* brv[2] = {(const float*)d_in[7],  (const float*)d_in[14]};
    const float* We[2]  = {(const float*)d_in[8],  (const float*)d_in[15]};
    const float* att[2] = {(const float*)d_in[9],  (const float*)d_in[16]};
    const float* bo[2]  = {(const float*)d_in[10], (const float*)d_in[17]};

    void *pxl, *pxr, *preh, *ph1, *pdeg, *pcur;
    cudaGetSymbolAddress(&pxl, g_xl);
    cudaGetSymbolAddress(&pxr, g_xr);
    cudaGetSymbolAddress(&preh, g_reh);
    cudaGetSymbolAddress(&ph1, g_h1);
    cudaGetSymbolAddress(&pdeg, g_deg);
    cudaGetSymbolAddress(&pcur, g_cursor);

    cudaMemsetAsync(pdeg, 0, NN * sizeof(int));
    cudaMemsetAsync(pcur, 0, NN * sizeof(int));
    k_count<<<(EE + 255) / 256, 256>>>(ei);
    k_scan<<<1, 1024>>>();
    k_scatter<<<(EE + 255) / 256, 256>>>(ei);
    k_sortpack<<<(NN + 255) / 256, 256>>>(ei, relidx);

    const float* xin = x;
    for (int l = 0; l < 2; l++) {
        dim3 gtc((NN + 63) / 64, 4, 2);
        dim3 gr((RT + 127) / 128, 4);
        k_gemm_tc<<<gtc, 256>>>(xin, Wl[l], blv[l], (float*)pxl,
                                Wr[l], brv[l], (float*)pxr, NN);
        k_gemm_re<<<gr, 256>>>(relations, We[l], (__half2*)preh, RT);
        float* outp = (l == 0) ? (float*)ph1 : (float*)d_out;
        k_fused<<<(NN + 7) / 8, 256>>>(att[l], bo[l], outp);
        xin = (const float*)ph1;
    }
    if (out_size >= NN * 64 + RT * 64)
        cudaMemcpyAsync((float*)d_out + (size_t)NN * 64, relations,
                        (size_t)RT * 64 * sizeof(float), cudaMemcpyDeviceToDevice);
}

// round 8
// speedup vs baseline: 1.0763x; 1.0763x over previous
#include <cuda_runtime.h>
#include <cuda_fp16.h>
#include <math_constants.h>

#define NN   20000
#define EE   320000
#define RT   512
#define HC   256      // H*C

// ---------------- scratch (device globals: allocation-free) ----------------
__device__ float   g_xl[NN * HC];
__device__ float   g_xr[NN * HC];
__device__ __half2 g_reh[RT * 128];   // relations @ We^T, fp16 (128 half2 per row)
__device__ float   g_h1[NN * 64];     // layer-0 output
__device__ int     g_deg[NN];
__device__ int     g_rowptr[NN + 1];
__device__ int     g_cursor[NN];
__device__ int     g_csr[EE];
__device__ int2    g_srcrel[EE];      // (src, rel) per sorted CSR slot

// ---------------- CSR build ----------------
__global__ void k_count(const int* __restrict__ ei) {
    int i = blockIdx.x * blockDim.x + threadIdx.x;
    if (i < EE) atomicAdd(&g_deg[ei[EE + i]], 1);
}

__global__ void k_scan() {
    __shared__ int wsum[32];
    __shared__ int carry;
    int tid = threadIdx.x, lane = tid & 31, wid = tid >> 5;
    if (tid == 0) { carry = 0; g_rowptr[0] = 0; }
    __syncthreads();
    for (int base = 0; base < NN; base += 1024) {
        int i = base + tid;
        int x = (i < NN) ? g_deg[i] : 0;
#pragma unroll
        for (int off = 1; off < 32; off <<= 1) {
            int t = __shfl_up_sync(0xffffffffu, x, off);
            if (lane >= off) x += t;
        }
        if (lane == 31) wsum[wid] = x;
        __syncthreads();
        if (wid == 0) {
            int s = wsum[lane];
#pragma unroll
            for (int off = 1; off < 32; off <<= 1) {
                int t = __shfl_up_sync(0xffffffffu, s, off);
                if (lane >= off) s += t;
            }
            wsum[lane] = s;
        }
        __syncthreads();
        int total = wsum[31];
        int prefix = carry + (wid ? wsum[wid - 1] : 0) + x;
        if (i < NN) g_rowptr[i + 1] = prefix;
        __syncthreads();
        if (tid == 0) carry += total;
        __syncthreads();
    }
}

__global__ void k_scatter(const int* __restrict__ ei) {
    int i = blockIdx.x * blockDim.x + threadIdx.x;
    if (i >= EE) return;
    int d = ei[EE + i];
    int pos = atomicAdd(&g_cursor[d], 1);
    g_csr[g_rowptr[d] + pos] = i;
}

// warp-per-node: bitonic sort (64 elems, 2 regs/lane) + parallel (src,rel) pack
__global__ __launch_bounds__(256) void k_sortpack(const int* __restrict__ ei,
                                                  const int* __restrict__ relidx) {
    int w = (blockIdx.x * blockDim.x + threadIdx.x) >> 5;
    int lane = threadIdx.x & 31;
    if (w >= NN) return;
    int beg = g_rowptr[w], end = g_rowptr[w + 1];
    int len = end - beg;

    if (len <= 64) {
        int v0 = (beg + lane < end)      ? g_csr[beg + lane]      : 0x7fffffff;
        int v1 = (beg + 32 + lane < end) ? g_csr[beg + 32 + lane] : 0x7fffffff;
        // bitonic sort of 64: j0 = lane, j1 = lane + 32
#pragma unroll
        for (int k = 2; k <= 64; k <<= 1) {
#pragma unroll
            for (int d = k >> 1; d > 0; d >>= 1) {
                if (d == 32) {
                    // only occurs for k=64 (ascending): pairwise min/max across slots
                    int lo = min(v0, v1), hi = max(v0, v1);
                    v0 = lo; v1 = hi;
                } else {
                    bool lower = ((lane & d) == 0);
                    bool up0 = ((lane & k) == 0);
                    bool up1 = (((lane + 32) & k) == 0);
                    int p0 = __shfl_xor_sync(0xffffffffu, v0, d);
                    int p1 = __shfl_xor_sync(0xffffffffu, v1, d);
                    v0 = (lower == up0) ? min(v0, p0) : max(v0, p0);
                    v1 = (lower == up1) ? min(v1, p1) : max(v1, p1);
                }
            }
        }
        if (lane < len) {
            int e = v0;
            g_srcrel[beg + lane] = make_int2(ei[e], relidx[e]);
        }
        if (32 + lane < len) {
            int e = v1;
            g_srcrel[beg + 32 + lane] = make_int2(ei[e], relidx[e]);
        }
    } else {
        // practically unreachable fallback (deg > 64)
        if (lane == 0) {
            for (int i = beg + 1; i < end; i++) {
                int v = g_csr[i];
                int j = i - 1;
                while (j >= beg && g_csr[j] > v) { g_csr[j + 1] = g_csr[j]; j--; }
                g_csr[j + 1] = v;
            }
        }
        __syncwarp();
        for (int i = beg + lane; i < end; i += 32) {
            int e = g_csr[i];
            g_srcrel[i] = make_int2(ei[e], relidx[e]);
        }
    }
}

// ---------------- tf32 helpers ----------------
__device__ __forceinline__ unsigned f2tf32(float f) {
    unsigned u;
    asm("cvt.rna.tf32.f32 %0, %1;" : "=r"(u) : "f"(f));
    return u;
}
__device__ __forceinline__ void mma_tf32(float& c0, float& c1, float& c2, float& c3,
                                         unsigned a0, unsigned a1, unsigned a2, unsigned a3,
                                         unsigned b0, unsigned b1) {
    asm("mma.sync.aligned.m16n8k8.row.col.f32.tf32.tf32.f32 "
        "{%0,%1,%2,%3},{%4,%5,%6,%7},{%8,%9},{%0,%1,%2,%3};"
        : "+f"(c0), "+f"(c1), "+f"(c2), "+f"(c3)
        : "r"(a0), "r"(a1), "r"(a2), "r"(a3), "r"(b0), "r"(b1));
}

// ---- tensor-core GEMM: out[M,256] = A[M,64] @ W[256,64]^T + bias ----
__global__ __launch_bounds__(256) void k_gemm_tc(const float* __restrict__ A,
                                                 const float* __restrict__ W0,
                                                 const float* __restrict__ bias0,
                                                 float* __restrict__ out0,
                                                 const float* __restrict__ W1,
                                                 const float* __restrict__ bias1,
                                                 float* __restrict__ out1, int M) {
    const float* W    = blockIdx.z ? W1 : W0;
    const float* bias = blockIdx.z ? bias1 : bias0;
    float* out        = blockIdx.z ? out1 : out0;
    __shared__ unsigned As[64][68];
    __shared__ unsigned Ws[64][68];
    int tid = threadIdx.x;
    int row0 = blockIdx.x * 64, n0 = blockIdx.y * 64;

#pragma unroll
    for (int it = 0; it < 4; it++) {
        int idx = tid + it * 256;
        int r = idx >> 4, k4 = idx & 15;
        int m = row0 + r;
        float4 v = (m < M) ? *(const float4*)(A + (size_t)m * 64 + k4 * 4)
                           : make_float4(0.f, 0.f, 0.f, 0.f);
        As[r][k4 * 4 + 0] = f2tf32(v.x); As[r][k4 * 4 + 1] = f2tf32(v.y);
        As[r][k4 * 4 + 2] = f2tf32(v.z); As[r][k4 * 4 + 3] = f2tf32(v.w);
        float4 wv = *(const float4*)(W + (size_t)(n0 + r) * 64 + k4 * 4);
        Ws[r][k4 * 4 + 0] = f2tf32(wv.x); Ws[r][k4 * 4 + 1] = f2tf32(wv.y);
        Ws[r][k4 * 4 + 2] = f2tf32(wv.z); Ws[r][k4 * 4 + 3] = f2tf32(wv.w);
    }
    __syncthreads();

    int wid = tid >> 5, lane = tid & 31;
    int g = lane >> 2, tig = lane & 3;
    int rbase = (wid & 3) * 16;
    int ncb = (wid >> 2) * 32;
    float acc[4][4] = {};
#pragma unroll
    for (int ks = 0; ks < 8; ks++) {
        int k0 = ks * 8;
        unsigned a0 = As[rbase + g][k0 + tig];
        unsigned a1 = As[rbase + g + 8][k0 + tig];
        unsigned a2 = As[rbase + g][k0 + tig + 4];
        unsigned a3 = As[rbase + g + 8][k0 + tig + 4];
#pragma unroll
        for (int nt = 0; nt < 4; nt++) {
            unsigned b0 = Ws[ncb + nt * 8 + g][k0 + tig];
            unsigned b1 = Ws[ncb + nt * 8 + g][k0 + tig + 4];
            mma_tf32(acc[nt][0], acc[nt][1], acc[nt][2], acc[nt][3],
                     a0, a1, a2, a3, b0, b1);
        }
    }
    int m0 = row0 + rbase + g;
#pragma unroll
    for (int nt = 0; nt < 4; nt++) {
        int gcol = n0 + ncb + nt * 8 + tig * 2;
        float2 bv = *(const float2*)(bias + gcol);
        if (m0 < M)
            *(float2*)(out + (size_t)m0 * 256 + gcol) =
                make_float2(acc[nt][0] + bv.x, acc[nt][1] + bv.y);
        if (m0 + 8 < M)
            *(float2*)(out + (size_t)(m0 + 8) * 256 + gcol) =
                make_float2(acc[nt][2] + bv.x, acc[nt][3] + bv.y);
    }
}

// ---- scalar fp32 GEMM -> fp16 output (relations @ We^T) ----
__global__ __launch_bounds__(256) void k_gemm_re(const float* __restrict__ A,
                                                 const float* __restrict__ W,
                                                 __half2* __restrict__ out, int M) {
    __shared__ float xsT[32][132];
    __shared__ float Ws[32][68];
    int tid = threadIdx.x;
    int row0 = blockIdx.x * 128, n0 = blockIdx.y * 64;
    int rg = tid >> 4, cg = tid & 15;
    int r0 = rg * 8, c0 = cg * 4;
    float acc[8][4] = {};

    for (int kc = 0; kc < 64; kc += 32) {
#pragma unroll
        for (int it = 0; it < 4; ++it) {
            int idx = tid + it * 256;
            int r = idx >> 3, k4 = idx & 7;
            int m = row0 + r;
            float4 v = (m < M) ? *(const float4*)(A + (size_t)m * 64 + kc + k4 * 4)
                               : make_float4(0.f, 0.f, 0.f, 0.f);
            xsT[k4 * 4 + 0][r] = v.x; xsT[k4 * 4 + 1][r] = v.y;
            xsT[k4 * 4 + 2][r] = v.z; xsT[k4 * 4 + 3][r] = v.w;
        }
#pragma unroll
        for (int it = 0; it < 2; ++it) {
            int idx = tid + it * 256;
            int n = idx >> 3, k4 = idx & 7;
            float4 v = *(const float4*)(W + (size_t)(n0 + n) * 64 + kc + k4 * 4);
            Ws[k4 * 4 + 0][n] = v.x; Ws[k4 * 4 + 1][n] = v.y;
            Ws[k4 * 4 + 2][n] = v.z; Ws[k4 * 4 + 3][n] = v.w;
        }
        __syncthreads();
#pragma unroll
        for (int k = 0; k < 32; k++) {
            float4 x0 = *(const float4*)&xsT[k][r0];
            float4 x1 = *(const float4*)&xsT[k][r0 + 4];
            float4 wv = *(const float4*)&Ws[k][c0];
            float xv[8] = {x0.x, x0.y, x0.z, x0.w, x1.x, x1.y, x1.z, x1.w};
#pragma unroll
            for (int r = 0; r < 8; r++) {
                acc[r][0] += xv[r] * wv.x; acc[r][1] += xv[r] * wv.y;
                acc[r][2] += xv[r] * wv.z; acc[r][3] += xv[r] * wv.w;
            }
        }
        __syncthreads();
    }
#pragma unroll
    for (int r = 0; r < 8; r++) {
        int m = row0 + r0 + r;
        if (m < M) {
            __half2 h0 = __floats2half2_rn(acc[r][0], acc[r][1]);
            __half2 h1 = __floats2half2_rn(acc[r][2], acc[r][3]);
            *(uint2*)(out + (size_t)m * 128 + (n0 + c0) / 2) =
                make_uint2(*(unsigned*)&h0, *(unsigned*)&h1);
        }
    }
}

// ---------------- fused alpha + online softmax + aggregation + self-loop ----------
struct Rows { float4 xlA, xlB, eeA, eeB; };

__device__ __forceinline__ float4 h4_to_f4(uint2 u) {
    __half2 h0 = *(__half2*)&u.x, h1 = *(__half2*)&u.y;
    float2 lo = __half22float2(h0), hi = __half22float2(h1);
    return make_float4(lo.x, lo.y, hi.x, hi.y);
}

__device__ __forceinline__ void load_rows(Rows& r, int src, int rel, int lane) {
    const float* xlp = g_xl + (size_t)src * HC;
    const __half2* eep = g_reh + (size_t)rel * 128;
    r.xlA = *(const float4*)(xlp + 4 * lane);
    r.xlB = *(const float4*)(xlp + 128 + 4 * lane);
    r.eeA = h4_to_f4(*(const uint2*)(eep + 2 * lane));
    r.eeB = h4_to_f4(*(const uint2*)(eep + 64 + 2 * lane));
}

__device__ __forceinline__ void logits(const Rows& r, float4 xrA, float4 xrB,
                                       float4 attA, float4 attB,
                                       float& pA, float& pB) {
    float t;
    t = r.xlA.x + xrA.x + r.eeA.x; t = t > 0.f ? t : 0.2f * t; pA  = t * attA.x;
    t = r.xlA.y + xrA.y + r.eeA.y; t = t > 0.f ? t : 0.2f * t; pA += t * attA.y;
    t = r.xlA.z + xrA.z + r.eeA.z; t = t > 0.f ? t : 0.2f * t; pA += t * attA.z;
    t = r.xlA.w + xrA.w + r.eeA.w; t = t > 0.f ? t : 0.2f * t; pA += t * attA.w;
    t = r.xlB.x + xrB.x + r.eeB.x; t = t > 0.f ? t : 0.2f * t; pB  = t * attB.x;
    t = r.xlB.y + xrB.y + r.eeB.y; t = t > 0.f ? t : 0.2f * t; pB += t * attB.y;
    t = r.xlB.z + xrB.z + r.eeB.z; t = t > 0.f ? t : 0.2f * t; pB += t * attB.z;
    t = r.xlB.w + xrB.w + r.eeB.w; t = t > 0.f ? t : 0.2f * t; pB += t * attB.w;
}

__device__ __forceinline__ void online_update(float pA, float pB, const Rows& r,
                                              float& mA, float& mB, float& sA, float& sB,
                                              float4& accA, float4& accB) {
    float nm = fmaxf(mA, pA);
    float scl = __expf(mA - nm);
    float wgt = __expf(pA - nm);
    sA = sA * scl + wgt;
    accA.x = accA.x * scl + wgt * r.xlA.x;
    accA.y = accA.y * scl + wgt * r.xlA.y;
    accA.z = accA.z * scl + wgt * r.xlA.z;
    accA.w = accA.w * scl + wgt * r.xlA.w;
    mA = nm;
    nm = fmaxf(mB, pB);
    scl = __expf(mB - nm);
    wgt = __expf(pB - nm);
    sB = sB * scl + wgt;
    accB.x = accB.x * scl + wgt * r.xlB.x;
    accB.y = accB.y * scl + wgt * r.xlB.y;
    accB.z = accB.z * scl + wgt * r.xlB.z;
    accB.w = accB.w * scl + wgt * r.xlB.w;
    mB = nm;
}

__global__ __launch_bounds__(256) void k_fused(const float* __restrict__ att,
                                               const float* __restrict__ bias,
                                               float* __restrict__ out) {
    int w = (blockIdx.x * blockDim.x + threadIdx.x) >> 5;
    int lane = threadIdx.x & 31;
    if (w >= NN) return;
    int beg = g_rowptr[w], end = g_rowptr[w + 1];

    float4 attA = *(const float4*)(att + ((lane >> 4) * 64) + (lane & 15) * 4);
    float4 attB = *(const float4*)(att + 128 + ((lane >> 4) * 64) + (lane & 15) * 4);

    const float* xrp = g_xr + (size_t)w * HC;
    float4 xrA = *(const float4*)(xrp + 4 * lane);
    float4 xrB = *(const float4*)(xrp + 128 + 4 * lane);

    float mA = -CUDART_INF_F, mB = -CUDART_INF_F;
    float sA = 0.f, sB = 0.f;
    float4 accA = make_float4(0.f, 0.f, 0.f, 0.f);
    float4 accB = make_float4(0.f, 0.f, 0.f, 0.f);
    float4 esA = make_float4(0.f, 0.f, 0.f, 0.f);
    float4 esB = make_float4(0.f, 0.f, 0.f, 0.f);

    int i = beg;
    for (; i + 2 <= end; i += 2) {
        int2 sr0 = g_srcrel[i];
        int2 sr1 = g_srcrel[i + 1];
        Rows r0, r1;
        load_rows(r0, sr0.x, sr0.y, lane);
        load_rows(r1, sr1.x, sr1.y, lane);
        esA.x += r0.eeA.x; esA.y += r0.eeA.y; esA.z += r0.eeA.z; esA.w += r0.eeA.w;
        esB.x += r0.eeB.x; esB.y += r0.eeB.y; esB.z += r0.eeB.z; esB.w += r0.eeB.w;
        esA.x += r1.eeA.x; esA.y += r1.eeA.y; esA.z += r1.eeA.z; esA.w += r1.eeA.w;
        esB.x += r1.eeB.x; esB.y += r1.eeB.y; esB.z += r1.eeB.z; esB.w += r1.eeB.w;

        float p0A, p0B, p1A, p1B;
        logits(r0, xrA, xrB, attA, attB, p0A, p0B);
        logits(r1, xrA, xrB, attA, attB, p1A, p1B);
#pragma unroll
        for (int off = 1; off < 16; off <<= 1) {
            p0A += __shfl_xor_sync(0xffffffffu, p0A, off);
            p0B += __shfl_xor_sync(0xffffffffu, p0B, off);
            p1A += __shfl_xor_sync(0xffffffffu, p1A, off);
            p1B += __shfl_xor_sync(0xffffffffu, p1B, off);
        }
        online_update(p0A, p0B, r0, mA, mB, sA, sB, accA, accB);
        online_update(p1A, p1B, r1, mA, mB, sA, sB, accA, accB);
    }
    if (i < end) {
        int2 sr = g_srcrel[i];
        Rows r;
        load_rows(r, sr.x, sr.y, lane);
        esA.x += r.eeA.x; esA.y += r.eeA.y; esA.z += r.eeA.z; esA.w += r.eeA.w;
        esB.x += r.eeB.x; esB.y += r.eeB.y; esB.z += r.eeB.z; esB.w += r.eeB.w;
        float pA, pB;
        logits(r, xrA, xrB, attA, attB, pA, pB);
#pragma unroll
        for (int off = 1; off < 16; off <<= 1) {
            pA += __shfl_xor_sync(0xffffffffu, pA, off);
            pB += __shfl_xor_sync(0xffffffffu, pB, off);
        }
        online_update(pA, pB, r, mA, mB, sA, sB, accA, accB);
    }

    {   // self-loop: ee = mean of incoming ee rows, xl = xl[w]
        int deg = end - beg;
        float inv = 1.f / (float)(deg > 1 ? deg : 1);
        Rows r;
        r.eeA = make_float4(esA.x * inv, esA.y * inv, esA.z * inv, esA.w * inv);
        r.eeB = make_float4(esB.x * inv, esB.y * inv, esB.z * inv, esB.w * inv);
        const float* xlp = g_xl + (size_t)w * HC;
        r.xlA = *(const float4*)(xlp + 4 * lane);
        r.xlB = *(const float4*)(xlp + 128 + 4 * lane);
        float pA, pB;
        logits(r, xrA, xrB, attA, attB, pA, pB);
#pragma unroll
        for (int off = 1; off < 16; off <<= 1) {
            pA += __shfl_xor_sync(0xffffffffu, pA, off);
            pB += __shfl_xor_sync(0xffffffffu, pB, off);
        }
        online_update(pA, pB, r, mA, mB, sA, sB, accA, accB);
    }

    float iA = 1.f / sA, iB = 1.f / sB;
    accA.x *= iA; accA.y *= iA; accA.z *= iA; accA.w *= iA;
    accB.x *= iB; accB.y *= iB; accB.z *= iB; accB.w *= iB;
    accA.x += __shfl_xor_sync(0xffffffffu, accA.x, 16);
    accA.y += __shfl_xor_sync(0xffffffffu, accA.y, 16);
    accA.z += __shfl_xor_sync(0xffffffffu, accA.z, 16);
    accA.w += __shfl_xor_sync(0xffffffffu, accA.w, 16);
    accB.x += __shfl_xor_sync(0xffffffffu, accB.x, 16);
    accB.y += __shfl_xor_sync(0xffffffffu, accB.y, 16);
    accB.z += __shfl_xor_sync(0xffffffffu, accB.z, 16);
    accB.w += __shfl_xor_sync(0xffffffffu, accB.w, 16);
    if (lane < 16) {
        float4 bv = *(const float4*)(bias + 4 * lane);
        float4 o;
        o.x = 0.25f * (accA.x + accB.x) + bv.x;
        o.y = 0.25f * (accA.y + accB.y) + bv.y;
        o.z = 0.25f * (accA.z + accB.z) + bv.z;
        o.w = 0.25f * (accA.w + accB.w) + bv.w;
        *(float4*)(out + (size_t)w * 64 + 4 * lane) = o;
    }
}

// ---------------- host ----------------
extern "C" void kernel_launch(void* const* d_in, const int* in_sizes, int n_in,
                              void* d_out, int out_size) {
    const float* x         = (const float*)d_in[0];
    const int* ei          = (const int*)d_in[1];
    const float* relations = (const float*)d_in[2];
    const int* relidx      = (const int*)d_in[3];
    const float* Wl[2]  = {(const float*)d_in[4],  (const float*)d_in[11]};
    const float* blv[2] = {(const float*)d_in[5],  (const float*)d_in[12]};
    const float* Wr[2]  = {(const float*)d_in[6],  (const float*)d_in[13]};
    const float* brv[2] = {(const float*)d_in[7],  (const float*)d_in[14]};
    const float* We[2]  = {(const float*)d_in[8],  (const float*)d_in[15]};
    const float* att[2] = {(const float*)d_in[9],  (const float*)d_in[16]};
    const float* bo[2]  = {(const float*)d_in[10], (const float*)d_in[17]};

    void *pxl, *pxr, *preh, *ph1, *pdeg, *pcur;
    cudaGetSymbolAddress(&pxl, g_xl);
    cudaGetSymbolAddress(&pxr, g_xr);
    cudaGetSymbolAddress(&preh, g_reh);
    cudaGetSymbolAddress(&ph1, g_h1);
    cudaGetSymbolAddress(&pdeg, g_deg);
    cudaGetSymbolAddress(&pcur, g_cursor);

    cudaMemsetAsync(pdeg, 0, NN * sizeof(int));
    cudaMemsetAsync(pcur, 0, NN * sizeof(int));
    k_count<<<(EE + 255) / 256, 256>>>(ei);
    k_scan<<<1, 1024>>>();
    k_scatter<<<(EE + 255) / 256, 256>>>(ei);
    k_sortpack<<<(NN * 32 + 255) / 256, 256>>>(ei, relidx);

    const float* xin = x;
    for (int l = 0; l < 2; l++) {
        dim3 gtc((NN + 63) / 64, 4, 2);
        dim3 gr((RT + 127) / 128, 4);
        k_gemm_tc<<<gtc, 256>>>(xin, Wl[l], blv[l], (float*)pxl,
                                Wr[l], brv[l], (float*)pxr, NN);
        k_gemm_re<<<gr, 256>>>(relations, We[l], (__half2*)preh, RT);
        float* outp = (l == 0) ? (float*)ph1 : (float*)d_out;
        k_fused<<<(NN + 7) / 8, 256>>>(att[l], bo[l], outp);
        xin = (const float*)ph1;
    }
    if (out_size >= NN * 64 + RT * 64)
        cudaMemcpyAsync((float*)d_out + (size_t)NN * 64, relations,
                        (size_t)RT * 64 * sizeof(float), cudaMemcpyDeviceToDevice);
}

// round 9
// speedup vs baseline: 1.1210x; 1.0416x over previous
#include <cuda_runtime.h>
#include <cuda_fp16.h>
#include <math_constants.h>

#define NN   20000
#define EE   320000
#define RT   512
#define HC   256      // H*C

// ---------------- scratch (device globals: allocation-free) ----------------
__device__ __half2 g_xlh[NN * 128];   // lin_l(x), fp16 (128 half2 per row)
__device__ float   g_xr[NN * HC];     // lin_r(x), fp32
__device__ __half2 g_reh[RT * 128];   // relations @ We^T, fp16
__device__ float   g_h1[NN * 64];     // layer-0 output
__device__ int     g_deg[NN];
__device__ int     g_rowptr[NN + 1];
__device__ int     g_cursor[NN];
__device__ int     g_csr[EE];
__device__ int2    g_srcrel[EE];      // (src, rel) per sorted CSR slot

// ---------------- CSR build ----------------
__global__ void k_count(const int* __restrict__ ei) {
    int i = blockIdx.x * blockDim.x + threadIdx.x;
    if (i < EE) atomicAdd(&g_deg[ei[EE + i]], 1);
}

__global__ void k_scan() {
    __shared__ int wsum[32];
    __shared__ int carry;
    int tid = threadIdx.x, lane = tid & 31, wid = tid >> 5;
    if (tid == 0) { carry = 0; g_rowptr[0] = 0; }
    __syncthreads();
    for (int base = 0; base < NN; base += 1024) {
        int i = base + tid;
        int x = (i < NN) ? g_deg[i] : 0;
#pragma unroll
        for (int off = 1; off < 32; off <<= 1) {
            int t = __shfl_up_sync(0xffffffffu, x, off);
            if (lane >= off) x += t;
        }
        if (lane == 31) wsum[wid] = x;
        __syncthreads();
        if (wid == 0) {
            int s = wsum[lane];
#pragma unroll
            for (int off = 1; off < 32; off <<= 1) {
                int t = __shfl_up_sync(0xffffffffu, s, off);
                if (lane >= off) s += t;
            }
            wsum[lane] = s;
        }
        __syncthreads();
        int total = wsum[31];
        int prefix = carry + (wid ? wsum[wid - 1] : 0) + x;
        if (i < NN) g_rowptr[i + 1] = prefix;
        __syncthreads();
        if (tid == 0) carry += total;
        __syncthreads();
    }
}

__global__ void k_scatter(const int* __restrict__ ei) {
    int i = blockIdx.x * blockDim.x + threadIdx.x;
    if (i >= EE) return;
    int d = ei[EE + i];
    int pos = atomicAdd(&g_cursor[d], 1);
    g_csr[g_rowptr[d] + pos] = i;
}

// warp-per-node: bitonic sort (64 elems, 2 regs/lane) + parallel (src,rel) pack
__global__ __launch_bounds__(256) void k_sortpack(const int* __restrict__ ei,
                                                  const int* __restrict__ relidx) {
    int w = (blockIdx.x * blockDim.x + threadIdx.x) >> 5;
    int lane = threadIdx.x & 31;
    if (w >= NN) return;
    int beg = g_rowptr[w], end = g_rowptr[w + 1];
    int len = end - beg;

    if (len <= 64) {
        int v0 = (beg + lane < end)      ? g_csr[beg + lane]      : 0x7fffffff;
        int v1 = (beg + 32 + lane < end) ? g_csr[beg + 32 + lane] : 0x7fffffff;
#pragma unroll
        for (int k = 2; k <= 64; k <<= 1) {
#pragma unroll
            for (int d = k >> 1; d > 0; d >>= 1) {
                if (d == 32) {
                    int lo = min(v0, v1), hi = max(v0, v1);
                    v0 = lo; v1 = hi;
                } else {
                    bool lower = ((lane & d) == 0);
                    bool up0 = ((lane & k) == 0);
                    bool up1 = (((lane + 32) & k) == 0);
                    int p0 = __shfl_xor_sync(0xffffffffu, v0, d);
                    int p1 = __shfl_xor_sync(0xffffffffu, v1, d);
                    v0 = (lower == up0) ? min(v0, p0) : max(v0, p0);
                    v1 = (lower == up1) ? min(v1, p1) : max(v1, p1);
                }
            }
        }
        if (lane < len) {
            int e = v0;
            g_srcrel[beg + lane] = make_int2(ei[e], relidx[e]);
        }
        if (32 + lane < len) {
            int e = v1;
            g_srcrel[beg + 32 + lane] = make_int2(ei[e], relidx[e]);
        }
    } else {
        if (lane == 0) {
            for (int i = beg + 1; i < end; i++) {
                int v = g_csr[i];
                int j = i - 1;
                while (j >= beg && g_csr[j] > v) { g_csr[j + 1] = g_csr[j]; j--; }
                g_csr[j + 1] = v;
            }
        }
        __syncwarp();
        for (int i = beg + lane; i < end; i += 32) {
            int e = g_csr[i];
            g_srcrel[i] = make_int2(ei[e], relidx[e]);
        }
    }
}

// ---------------- tf32 helpers ----------------
__device__ __forceinline__ unsigned f2tf32(float f) {
    unsigned u;
    asm("cvt.rna.tf32.f32 %0, %1;" : "=r"(u) : "f"(f));
    return u;
}
__device__ __forceinline__ void mma_tf32(float& c0, float& c1, float& c2, float& c3,
                                         unsigned a0, unsigned a1, unsigned a2, unsigned a3,
                                         unsigned b0, unsigned b1) {
    asm("mma.sync.aligned.m16n8k8.row.col.f32.tf32.tf32.f32 "
        "{%0,%1,%2,%3},{%4,%5,%6,%7},{%8,%9},{%0,%1,%2,%3};"
        : "+f"(c0), "+f"(c1), "+f"(c2), "+f"(c3)
        : "r"(a0), "r"(a1), "r"(a2), "r"(a3), "r"(b0), "r"(b1));
}

// ---- tensor-core GEMM: z=0 -> xl (fp16 out), z=1 -> xr (fp32 out) ----
__global__ __launch_bounds__(256) void k_gemm_tc(const float* __restrict__ A,
                                                 const float* __restrict__ W0,
                                                 const float* __restrict__ bias0,
                                                 __half2* __restrict__ outH,
                                                 const float* __restrict__ W1,
                                                 const float* __restrict__ bias1,
                                                 float* __restrict__ outF, int M) {
    int zsel = blockIdx.z;
    const float* W    = zsel ? W1 : W0;
    const float* bias = zsel ? bias1 : bias0;
    __shared__ unsigned As[64][68];
    __shared__ unsigned Ws[64][68];
    int tid = threadIdx.x;
    int row0 = blockIdx.x * 64, n0 = blockIdx.y * 64;

#pragma unroll
    for (int it = 0; it < 4; it++) {
        int idx = tid + it * 256;
        int r = idx >> 4, k4 = idx & 15;
        int m = row0 + r;
        float4 v = (m < M) ? *(const float4*)(A + (size_t)m * 64 + k4 * 4)
                           : make_float4(0.f, 0.f, 0.f, 0.f);
        As[r][k4 * 4 + 0] = f2tf32(v.x); As[r][k4 * 4 + 1] = f2tf32(v.y);
        As[r][k4 * 4 + 2] = f2tf32(v.z); As[r][k4 * 4 + 3] = f2tf32(v.w);
        float4 wv = *(const float4*)(W + (size_t)(n0 + r) * 64 + k4 * 4);
        Ws[r][k4 * 4 + 0] = f2tf32(wv.x); Ws[r][k4 * 4 + 1] = f2tf32(wv.y);
        Ws[r][k4 * 4 + 2] = f2tf32(wv.z); Ws[r][k4 * 4 + 3] = f2tf32(wv.w);
    }
    __syncthreads();

    int wid = tid >> 5, lane = tid & 31;
    int g = lane >> 2, tig = lane & 3;
    int rbase = (wid & 3) * 16;
    int ncb = (wid >> 2) * 32;
    float acc[4][4] = {};
#pragma unroll
    for (int ks = 0; ks < 8; ks++) {
        int k0 = ks * 8;
        unsigned a0 = As[rbase + g][k0 + tig];
        unsigned a1 = As[rbase + g + 8][k0 + tig];
        unsigned a2 = As[rbase + g][k0 + tig + 4];
        unsigned a3 = As[rbase + g + 8][k0 + tig + 4];
#pragma unroll
        for (int nt = 0; nt < 4; nt++) {
            unsigned b0 = Ws[ncb + nt * 8 + g][k0 + tig];
            unsigned b1 = Ws[ncb + nt * 8 + g][k0 + tig + 4];
            mma_tf32(acc[nt][0], acc[nt][1], acc[nt][2], acc[nt][3],
                     a0, a1, a2, a3, b0, b1);
        }
    }
    int m0 = row0 + rbase + g;
#pragma unroll
    for (int nt = 0; nt < 4; nt++) {
        int gcol = n0 + ncb + nt * 8 + tig * 2;
        float2 bv = *(const float2*)(bias + gcol);
        if (zsel == 0) {
            if (m0 < M)
                outH[(size_t)m0 * 128 + gcol / 2] =
                    __floats2half2_rn(acc[nt][0] + bv.x, acc[nt][1] + bv.y);
            if (m0 + 8 < M)
                outH[(size_t)(m0 + 8) * 128 + gcol / 2] =
                    __floats2half2_rn(acc[nt][2] + bv.x, acc[nt][3] + bv.y);
        } else {
            if (m0 < M)
                *(float2*)(outF + (size_t)m0 * 256 + gcol) =
                    make_float2(acc[nt][0] + bv.x, acc[nt][1] + bv.y);
            if (m0 + 8 < M)
                *(float2*)(outF + (size_t)(m0 + 8) * 256 + gcol) =
                    make_float2(acc[nt][2] + bv.x, acc[nt][3] + bv.y);
        }
    }
}

// ---- scalar fp32 GEMM -> fp16 output (relations @ We^T) ----
__global__ __launch_bounds__(256) void k_gemm_re(const float* __restrict__ A,
                                                 const float* __restrict__ W,
                                                 __half2* __restrict__ out, int M) {
    __shared__ float xsT[32][132];
    __shared__ float Ws[32][68];
    int tid = threadIdx.x;
    int row0 = blockIdx.x * 128, n0 = blockIdx.y * 64;
    int rg = tid >> 4, cg = tid & 15;
    int r0 = rg * 8, c0 = cg * 4;
    float acc[8][4] = {};

    for (int kc = 0; kc < 64; kc += 32) {
#pragma unroll
        for (int it = 0; it < 4; ++it) {
            int idx = tid + it * 256;
            int r = idx >> 3, k4 = idx & 7;
            int m = row0 + r;
            float4 v = (m < M) ? *(const float4*)(A + (size_t)m * 64 + kc + k4 * 4)
                               : make_float4(0.f, 0.f, 0.f, 0.f);
            xsT[k4 * 4 + 0][r] = v.x; xsT[k4 * 4 + 1][r] = v.y;
            xsT[k4 * 4 + 2][r] = v.z; xsT[k4 * 4 + 3][r] = v.w;
        }
#pragma unroll
        for (int it = 0; it < 2; ++it) {
            int idx = tid + it * 256;
            int n = idx >> 3, k4 = idx & 7;
            float4 v = *(const float4*)(W + (size_t)(n0 + n) * 64 + kc + k4 * 4);
            Ws[k4 * 4 + 0][n] = v.x; Ws[k4 * 4 + 1][n] = v.y;
            Ws[k4 * 4 + 2][n] = v.z; Ws[k4 * 4 + 3][n] = v.w;
        }
        __syncthreads();
#pragma unroll
        for (int k = 0; k < 32; k++) {
            float4 x0 = *(const float4*)&xsT[k][r0];
            float4 x1 = *(const float4*)&xsT[k][r0 + 4];
            float4 wv = *(const float4*)&Ws[k][c0];
            float xv[8] = {x0.x, x0.y, x0.z, x0.w, x1.x, x1.y, x1.z, x1.w};
#pragma unroll
            for (int r = 0; r < 8; r++) {
                acc[r][0] += xv[r] * wv.x; acc[r][1] += xv[r] * wv.y;
                acc[r][2] += xv[r] * wv.z; acc[r][3] += xv[r] * wv.w;
            }
        }
        __syncthreads();
    }
#pragma unroll
    for (int r = 0; r < 8; r++) {
        int m = row0 + r0 + r;
        if (m < M) {
            __half2 h0 = __floats2half2_rn(acc[r][0], acc[r][1]);
            __half2 h1 = __floats2half2_rn(acc[r][2], acc[r][3]);
            *(uint2*)(out + (size_t)m * 128 + (n0 + c0) / 2) =
                make_uint2(*(unsigned*)&h0, *(unsigned*)&h1);
        }
    }
}

// ---------------- fused alpha + online softmax + aggregation + self-loop ----------
struct Rows { float4 xlA, xlB, eeA, eeB; };

__device__ __forceinline__ float4 h4_to_f4(uint2 u) {
    __half2 h0 = *(__half2*)&u.x, h1 = *(__half2*)&u.y;
    float2 lo = __half22float2(h0), hi = __half22float2(h1);
    return make_float4(lo.x, lo.y, hi.x, hi.y);
}

__device__ __forceinline__ void load_rows(Rows& r, int src, int rel, int lane) {
    const __half2* xlp = g_xlh + (size_t)src * 128;
    const __half2* eep = g_reh + (size_t)rel * 128;
    r.xlA = h4_to_f4(*(const uint2*)(xlp + 2 * lane));
    r.xlB = h4_to_f4(*(const uint2*)(xlp + 64 + 2 * lane));
    r.eeA = h4_to_f4(*(const uint2*)(eep + 2 * lane));
    r.eeB = h4_to_f4(*(const uint2*)(eep + 64 + 2 * lane));
}

__device__ __forceinline__ void logits(const Rows& r, float4 xrA, float4 xrB,
                                       float4 attA, float4 attB,
                                       float& pA, float& pB) {
    float t;
    t = r.xlA.x + xrA.x + r.eeA.x; t = t > 0.f ? t : 0.2f * t; pA  = t * attA.x;
    t = r.xlA.y + xrA.y + r.eeA.y; t = t > 0.f ? t : 0.2f * t; pA += t * attA.y;
    t = r.xlA.z + xrA.z + r.eeA.z; t = t > 0.f ? t : 0.2f * t; pA += t * attA.z;
    t = r.xlA.w + xrA.w + r.eeA.w; t = t > 0.f ? t : 0.2f * t; pA += t * attA.w;
    t = r.xlB.x + xrB.x + r.eeB.x; t = t > 0.f ? t : 0.2f * t; pB  = t * attB.x;
    t = r.xlB.y + xrB.y + r.eeB.y; t = t > 0.f ? t : 0.2f * t; pB += t * attB.y;
    t = r.xlB.z + xrB.z + r.eeB.z; t = t > 0.f ? t : 0.2f * t; pB += t * attB.z;
    t = r.xlB.w + xrB.w + r.eeB.w; t = t > 0.f ? t : 0.2f * t; pB += t * attB.w;
}

__device__ __forceinline__ void online_update(float pA, float pB, const Rows& r,
                                              float& mA, float& mB, float& sA, float& sB,
                                              float4& accA, float4& accB) {
    float nm = fmaxf(mA, pA);
    float scl = __expf(mA - nm);
    float wgt = __expf(pA - nm);
    sA = sA * scl + wgt;
    accA.x = accA.x * scl + wgt * r.xlA.x;
    accA.y = accA.y * scl + wgt * r.xlA.y;
    accA.z = accA.z * scl + wgt * r.xlA.z;
    accA.w = accA.w * scl + wgt * r.xlA.w;
    mA = nm;
    nm = fmaxf(mB, pB);
    scl = __expf(mB - nm);
    wgt = __expf(pB - nm);
    sB = sB * scl + wgt;
    accB.x = accB.x * scl + wgt * r.xlB.x;
    accB.y = accB.y * scl + wgt * r.xlB.y;
    accB.z = accB.z * scl + wgt * r.xlB.z;
    accB.w = accB.w * scl + wgt * r.xlB.w;
    mB = nm;
}

__global__ __launch_bounds__(256) void k_fused(const float* __restrict__ att,
                                               const float* __restrict__ bias,
                                               float* __restrict__ out) {
    int w = (blockIdx.x * blockDim.x + threadIdx.x) >> 5;
    int lane = threadIdx.x & 31;
    if (w >= NN) return;
    int beg = g_rowptr[w], end = g_rowptr[w + 1];

    float4 attA = *(const float4*)(att + ((lane >> 4) * 64) + (lane & 15) * 4);
    float4 attB = *(const float4*)(att + 128 + ((lane >> 4) * 64) + (lane & 15) * 4);

    const float* xrp = g_xr + (size_t)w * HC;
    float4 xrA = *(const float4*)(xrp + 4 * lane);
    float4 xrB = *(const float4*)(xrp + 128 + 4 * lane);

    float mA = -CUDART_INF_F, mB = -CUDART_INF_F;
    float sA = 0.f, sB = 0.f;
    float4 accA = make_float4(0.f, 0.f, 0.f, 0.f);
    float4 accB = make_float4(0.f, 0.f, 0.f, 0.f);
    float4 esA = make_float4(0.f, 0.f, 0.f, 0.f);
    float4 esB = make_float4(0.f, 0.f, 0.f, 0.f);

    int i = beg;
    for (; i + 2 <= end; i += 2) {
        int2 sr0 = g_srcrel[i];
        int2 sr1 = g_srcrel[i + 1];
        Rows r0, r1;
        load_rows(r0, sr0.x, sr0.y, lane);
        load_rows(r1, sr1.x, sr1.y, lane);
        esA.x += r0.eeA.x; esA.y += r0.eeA.y; esA.z += r0.eeA.z; esA.w += r0.eeA.w;
        esB.x += r0.eeB.x; esB.y += r0.eeB.y; esB.z += r0.eeB.z; esB.w += r0.eeB.w;
        esA.x += r1.eeA.x; esA.y += r1.eeA.y; esA.z += r1.eeA.z; esA.w += r1.eeA.w;
        esB.x += r1.eeB.x; esB.y += r1.eeB.y; esB.z += r1.eeB.z; esB.w += r1.eeB.w;

        float p0A, p0B, p1A, p1B;
        logits(r0, xrA, xrB, attA, attB, p0A, p0B);
        logits(r1, xrA, xrB, attA, attB, p1A, p1B);
#pragma unroll
        for (int off = 1; off < 16; off <<= 1) {
            p0A += __shfl_xor_sync(0xffffffffu, p0A, off);
            p0B += __shfl_xor_sync(0xffffffffu, p0B, off);
            p1A += __shfl_xor_sync(0xffffffffu, p1A, off);
            p1B += __shfl_xor_sync(0xffffffffu, p1B, off);
        }
        online_update(p0A, p0B, r0, mA, mB, sA, sB, accA, accB);
        online_update(p1A, p1B, r1, mA, mB, sA, sB, accA, accB);
    }
    if (i < end) {
        int2 sr = g_srcrel[i];
        Rows r;
        load_rows(r, sr.x, sr.y, lane);
        esA.x += r.eeA.x; esA.y += r.eeA.y; esA.z += r.eeA.z; esA.w += r.eeA.w;
        esB.x += r.eeB.x; esB.y += r.eeB.y; esB.z += r.eeB.z; esB.w += r.eeB.w;
        float pA, pB;
        logits(r, xrA, xrB, attA, attB, pA, pB);
#pragma unroll
        for (int off = 1; off < 16; off <<= 1) {
            pA += __shfl_xor_sync(0xffffffffu, pA, off);
            pB += __shfl_xor_sync(0xffffffffu, pB, off);
        }
        online_update(pA, pB, r, mA, mB, sA, sB, accA, accB);
    }

    {   // self-loop: ee = mean of incoming ee rows, xl = xl[w]
        int deg = end - beg;
        float inv = 1.f / (float)(deg > 1 ? deg : 1);
        Rows r;
        r.eeA = make_float4(esA.x * inv, esA.y * inv, esA.z * inv, esA.w * inv);
        r.eeB = make_float4(esB.x * inv, esB.y * inv, esB.z * inv, esB.w * inv);
        const __half2* xlp = g_xlh + (size_t)w * 128;
        r.xlA = h4_to_f4(*(const uint2*)(xlp + 2 * lane));
        r.xlB = h4_to_f4(*(const uint2*)(xlp + 64 + 2 * lane));
        float pA, pB;
        logits(r, xrA, xrB, attA, attB, pA, pB);
#pragma unroll
        for (int off = 1; off < 16; off <<= 1) {
            pA += __shfl_xor_sync(0xffffffffu, pA, off);
            pB += __shfl_xor_sync(0xffffffffu, pB, off);
        }
        online_update(pA, pB, r, mA, mB, sA, sB, accA, accB);
    }

    float iA = 1.f / sA, iB = 1.f / sB;
    accA.x *= iA; accA.y *= iA; accA.z *= iA; accA.w *= iA;
    accB.x *= iB; accB.y *= iB; accB.z *= iB; accB.w *= iB;
    accA.x += __shfl_xor_sync(0xffffffffu, accA.x, 16);
    accA.y += __shfl_xor_sync(0xffffffffu, accA.y, 16);
    accA.z += __shfl_xor_sync(0xffffffffu, accA.z, 16);
    accA.w += __shfl_xor_sync(0xffffffffu, accA.w, 16);
    accB.x += __shfl_xor_sync(0xffffffffu, accB.x, 16);
    accB.y += __shfl_xor_sync(0xffffffffu, accB.y, 16);
    accB.z += __shfl_xor_sync(0xffffffffu, accB.z, 16);
    accB.w += __shfl_xor_sync(0xffffffffu, accB.w, 16);
    if (lane < 16) {
        float4 bv = *(const float4*)(bias + 4 * lane);
        float4 o;
        o.x = 0.25f * (accA.x + accB.x) + bv.x;
        o.y = 0.25f * (accA.y + accB.y) + bv.y;
        o.z = 0.25f * (accA.z + accB.z) + bv.z;
        o.w = 0.25f * (accA.w + accB.w) + bv.w;
        *(float4*)(out + (size_t)w * 64 + 4 * lane) = o;
    }
}

// ---------------- host ----------------
extern "C" void kernel_launch(void* const* d_in, const int* in_sizes, int n_in,
                              void* d_out, int out_size) {
    const float* x         = (const float*)d_in[0];
    const int* ei          = (const int*)d_in[1];
    const float* relations = (const float*)d_in[2];
    const int* relidx      = (const int*)d_in[3];
    const float* Wl[2]  = {(const float*)d_in[4],  (const float*)d_in[11]};
    const float* blv[2] = {(const float*)d_in[5],  (const float*)d_in[12]};
    const float* Wr[2]  = {(const float*)d_in[6],  (const float*)d_in[13]};
    const float* brv[2] = {(const float*)d_in[7],  (const float*)d_in[14]};
    const float* We[2]  = {(const float*)d_in[8],  (const float*)d_in[15]};
    const float* att[2] = {(const float*)d_in[9],  (const float*)d_in[16]};
    const float* bo[2]  = {(const float*)d_in[10], (const float*)d_in[17]};

    void *pxlh, *pxr, *preh, *ph1, *pdeg, *pcur;
    cudaGetSymbolAddress(&pxlh, g_xlh);
    cudaGetSymbolAddress(&pxr, g_xr);
    cudaGetSymbolAddress(&preh, g_reh);
    cudaGetSymbolAddress(&ph1, g_h1);
    cudaGetSymbolAddress(&pdeg, g_deg);
    cudaGetSymbolAddress(&pcur, g_cursor);

    cudaMemsetAsync(pdeg, 0, NN * sizeof(int));
    cudaMemsetAsync(pcur, 0, NN * sizeof(int));
    k_count<<<(EE + 255) / 256, 256>>>(ei);
    k_scan<<<1, 1024>>>();
    k_scatter<<<(EE + 255) / 256, 256>>>(ei);
    k_sortpack<<<(NN * 32 + 255) / 256, 256>>>(ei, relidx);

    const float* xin = x;
    for (int l = 0; l < 2; l++) {
        dim3 gtc((NN + 63) / 64, 4, 2);
        dim3 gr((RT + 127) / 128, 4);
        k_gemm_tc<<<gtc, 256>>>(xin, Wl[l], blv[l], (__half2*)pxlh,
                                Wr[l], brv[l], (float*)pxr, NN);
        k_gemm_re<<<gr, 256>>>(relations, We[l], (__half2*)preh, RT);
        float* outp = (l == 0) ? (float*)ph1 : (float*)d_out;
        k_fused<<<(NN + 7) / 8, 256>>>(att[l], bo[l], outp);
        xin = (const float*)ph1;
    }
    if (out_size >= NN * 64 + RT * 64)
        cudaMemcpyAsync((float*)d_out + (size_t)NN * 64, relations,
                        (size_t)RT * 64 * sizeof(float), cudaMemcpyDeviceToDevice);
}

// round 10
// speedup vs baseline: 1.2227x; 1.0907x over previous
#include <cuda_runtime.h>
#include <cuda_fp16.h>
#include <math_constants.h>

#define NN   20000
#define EE   320000
#define RT   512
#define HC   256      // H*C

// ---------------- scratch (device globals: allocation-free) ----------------
__device__ __half2 g_xlh[NN * 128];   // lin_l(x), fp16 (128 half2 per row)
__device__ float   g_xr[NN * HC];     // lin_r(x), fp32
__device__ __half2 g_reh0[RT * 128];  // relations @ We0^T, fp16
__device__ __half2 g_reh1[RT * 128];  // relations @ We1^T, fp16
__device__ float   g_h1[NN * 64];     // layer-0 output
__device__ int     g_deg[NN];
__device__ int     g_rowptr[NN + 1];
__device__ int     g_cursor[NN];
__device__ int     g_csr[EE];
__device__ int2    g_srcrel[EE];      // (src, rel) per sorted CSR slot

// ---------------- CSR build ----------------
__global__ void k_count(const int* __restrict__ ei) {
    int i = blockIdx.x * blockDim.x + threadIdx.x;
    if (i < EE) atomicAdd(&g_deg[ei[EE + i]], 1);
}

__global__ void k_scan() {
    __shared__ int wsum[32];
    __shared__ int carry;
    int tid = threadIdx.x, lane = tid & 31, wid = tid >> 5;
    if (tid == 0) { carry = 0; g_rowptr[0] = 0; }
    __syncthreads();
    for (int base = 0; base < NN; base += 1024) {
        int i = base + tid;
        int x = (i < NN) ? g_deg[i] : 0;
#pragma unroll
        for (int off = 1; off < 32; off <<= 1) {
            int t = __shfl_up_sync(0xffffffffu, x, off);
            if (lane >= off) x += t;
        }
        if (lane == 31) wsum[wid] = x;
        __syncthreads();
        if (wid == 0) {
            int s = wsum[lane];
#pragma unroll
            for (int off = 1; off < 32; off <<= 1) {
                int t = __shfl_up_sync(0xffffffffu, s, off);
                if (lane >= off) s += t;
            }
            wsum[lane] = s;
        }
        __syncthreads();
        int total = wsum[31];
        int prefix = carry + (wid ? wsum[wid - 1] : 0) + x;
        if (i < NN) g_rowptr[i + 1] = prefix;
        __syncthreads();
        if (tid == 0) carry += total;
        __syncthreads();
    }
}

__global__ void k_scatter(const int* __restrict__ ei) {
    int i = blockIdx.x * blockDim.x + threadIdx.x;
    if (i >= EE) return;
    int d = ei[EE + i];
    int pos = atomicAdd(&g_cursor[d], 1);
    g_csr[g_rowptr[d] + pos] = i;
}

// warp-per-node: bitonic sort (64 elems, 2 regs/lane) + parallel (src,rel) pack
__global__ __launch_bounds__(256) void k_sortpack(const int* __restrict__ ei,
                                                  const int* __restrict__ relidx) {
    int w = (blockIdx.x * blockDim.x + threadIdx.x) >> 5;
    int lane = threadIdx.x & 31;
    if (w >= NN) return;
    int beg = g_rowptr[w], end = g_rowptr[w + 1];
    int len = end - beg;

    if (len <= 64) {
        int v0 = (beg + lane < end)      ? g_csr[beg + lane]      : 0x7fffffff;
        int v1 = (beg + 32 + lane < end) ? g_csr[beg + 32 + lane] : 0x7fffffff;
#pragma unroll
        for (int k = 2; k <= 64; k <<= 1) {
#pragma unroll
            for (int d = k >> 1; d > 0; d >>= 1) {
                if (d == 32) {
                    int lo = min(v0, v1), hi = max(v0, v1);
                    v0 = lo; v1 = hi;
                } else {
                    bool lower = ((lane & d) == 0);
                    bool up0 = ((lane & k) == 0);
                    bool up1 = (((lane + 32) & k) == 0);
                    int p0 = __shfl_xor_sync(0xffffffffu, v0, d);
                    int p1 = __shfl_xor_sync(0xffffffffu, v1, d);
                    v0 = (lower == up0) ? min(v0, p0) : max(v0, p0);
                    v1 = (lower == up1) ? min(v1, p1) : max(v1, p1);
                }
            }
        }
        if (lane < len) {
            int e = v0;
            g_srcrel[beg + lane] = make_int2(ei[e], relidx[e]);
        }
        if (32 + lane < len) {
            int e = v1;
            g_srcrel[beg + 32 + lane] = make_int2(ei[e], relidx[e]);
        }
    } else {
        if (lane == 0) {
            for (int i = beg + 1; i < end; i++) {
                int v = g_csr[i];
                int j = i - 1;
                while (j >= beg && g_csr[j] > v) { g_csr[j + 1] = g_csr[j]; j--; }
                g_csr[j + 1] = v;
            }
        }
        __syncwarp();
        for (int i = beg + lane; i < end; i += 32) {
            int e = g_csr[i];
            g_srcrel[i] = make_int2(ei[e], relidx[e]);
        }
    }
}

// ---------------- tf32 helpers ----------------
__device__ __forceinline__ unsigned f2tf32(float f) {
    unsigned u;
    asm("cvt.rna.tf32.f32 %0, %1;" : "=r"(u) : "f"(f));
    return u;
}
__device__ __forceinline__ void mma_tf32(float& c0, float& c1, float& c2, float& c3,
                                         unsigned a0, unsigned a1, unsigned a2, unsigned a3,
                                         unsigned b0, unsigned b1) {
    asm("mma.sync.aligned.m16n8k8.row.col.f32.tf32.tf32.f32 "
        "{%0,%1,%2,%3},{%4,%5,%6,%7},{%8,%9},{%0,%1,%2,%3};"
        : "+f"(c0), "+f"(c1), "+f"(c2), "+f"(c3)
        : "r"(a0), "r"(a1), "r"(a2), "r"(a3), "r"(b0), "r"(b1));
}

// ---- tensor-core GEMM: z=0 -> xl (fp16 out), z=1 -> xr (fp32 out) ----
__global__ __launch_bounds__(256) void k_gemm_tc(const float* __restrict__ A,
                                                 const float* __restrict__ W0,
                                                 const float* __restrict__ bias0,
                                                 __half2* __restrict__ outH,
                                                 const float* __restrict__ W1,
                                                 const float* __restrict__ bias1,
                                                 float* __restrict__ outF, int M) {
    int zsel = blockIdx.z;
    const float* W    = zsel ? W1 : W0;
    const float* bias = zsel ? bias1 : bias0;
    __shared__ unsigned As[64][68];
    __shared__ unsigned Ws[64][68];
    int tid = threadIdx.x;
    int row0 = blockIdx.x * 64, n0 = blockIdx.y * 64;

#pragma unroll
    for (int it = 0; it < 4; it++) {
        int idx = tid + it * 256;
        int r = idx >> 4, k4 = idx & 15;
        int m = row0 + r;
        float4 v = (m < M) ? *(const float4*)(A + (size_t)m * 64 + k4 * 4)
                           : make_float4(0.f, 0.f, 0.f, 0.f);
        As[r][k4 * 4 + 0] = f2tf32(v.x); As[r][k4 * 4 + 1] = f2tf32(v.y);
        As[r][k4 * 4 + 2] = f2tf32(v.z); As[r][k4 * 4 + 3] = f2tf32(v.w);
        float4 wv = *(const float4*)(W + (size_t)(n0 + r) * 64 + k4 * 4);
        Ws[r][k4 * 4 + 0] = f2tf32(wv.x); Ws[r][k4 * 4 + 1] = f2tf32(wv.y);
        Ws[r][k4 * 4 + 2] = f2tf32(wv.z); Ws[r][k4 * 4 + 3] = f2tf32(wv.w);
    }
    __syncthreads();

    int wid = tid >> 5, lane = tid & 31;
    int g = lane >> 2, tig = lane & 3;
    int rbase = (wid & 3) * 16;
    int ncb = (wid >> 2) * 32;
    float acc[4][4] = {};
#pragma unroll
    for (int ks = 0; ks < 8; ks++) {
        int k0 = ks * 8;
        unsigned a0 = As[rbase + g][k0 + tig];
        unsigned a1 = As[rbase + g + 8][k0 + tig];
        unsigned a2 = As[rbase + g][k0 + tig + 4];
        unsigned a3 = As[rbase + g + 8][k0 + tig + 4];
#pragma unroll
        for (int nt = 0; nt < 4; nt++) {
            unsigned b0 = Ws[ncb + nt * 8 + g][k0 + tig];
            unsigned b1 = Ws[ncb + nt * 8 + g][k0 + tig + 4];
            mma_tf32(acc[nt][0], acc[nt][1], acc[nt][2], acc[nt][3],
                     a0, a1, a2, a3, b0, b1);
        }
    }
    int m0 = row0 + rbase + g;
#pragma unroll
    for (int nt = 0; nt < 4; nt++) {
        int gcol = n0 + ncb + nt * 8 + tig * 2;
        float2 bv = *(const float2*)(bias + gcol);
        if (zsel == 0) {
            if (m0 < M)
                outH[(size_t)m0 * 128 + gcol / 2] =
                    __floats2half2_rn(acc[nt][0] + bv.x, acc[nt][1] + bv.y);
            if (m0 + 8 < M)
                outH[(size_t)(m0 + 8) * 128 + gcol / 2] =
                    __floats2half2_rn(acc[nt][2] + bv.x, acc[nt][3] + bv.y);
        } else {
            if (m0 < M)
                *(float2*)(outF + (size_t)m0 * 256 + gcol) =
                    make_float2(acc[nt][0] + bv.x, acc[nt][1] + bv.y);
            if (m0 + 8 < M)
                *(float2*)(outF + (size_t)(m0 + 8) * 256 + gcol) =
                    make_float2(acc[nt][2] + bv.x, acc[nt][3] + bv.y);
        }
    }
}

// ---- scalar fp32 GEMM -> fp16 output (relations @ We^T) ----
__global__ __launch_bounds__(256) void k_gemm_re(const float* __restrict__ A,
                                                 const float* __restrict__ W,
                                                 __half2* __restrict__ out, int M) {
    __shared__ float xsT[32][132];
    __shared__ float Ws[32][68];
    int tid = threadIdx.x;
    int row0 = blockIdx.x * 128, n0 = blockIdx.y * 64;
    int rg = tid >> 4, cg = tid & 15;
    int r0 = rg * 8, c0 = cg * 4;
    float acc[8][4] = {};

    for (int kc = 0; kc < 64; kc += 32) {
#pragma unroll
        for (int it = 0; it < 4; ++it) {
            int idx = tid + it * 256;
            int r = idx >> 3, k4 = idx & 7;
            int m = row0 + r;
            float4 v = (m < M) ? *(const float4*)(A + (size_t)m * 64 + kc + k4 * 4)
                               : make_float4(0.f, 0.f, 0.f, 0.f);
            xsT[k4 * 4 + 0][r] = v.x; xsT[k4 * 4 + 1][r] = v.y;
            xsT[k4 * 4 + 2][r] = v.z; xsT[k4 * 4 + 3][r] = v.w;
        }
#pragma unroll
        for (int it = 0; it < 2; ++it) {
            int idx = tid + it * 256;
            int n = idx >> 3, k4 = idx & 7;
            float4 v = *(const float4*)(W + (size_t)(n0 + n) * 64 + kc + k4 * 4);
            Ws[k4 * 4 + 0][n] = v.x; Ws[k4 * 4 + 1][n] = v.y;
            Ws[k4 * 4 + 2][n] = v.z; Ws[k4 * 4 + 3][n] = v.w;
        }
        __syncthreads();
#pragma unroll
        for (int k = 0; k < 32; k++) {
            float4 x0 = *(const float4*)&xsT[k][r0];
            float4 x1 = *(const float4*)&xsT[k][r0 + 4];
            float4 wv = *(const float4*)&Ws[k][c0];
            float xv[8] = {x0.x, x0.y, x0.z, x0.w, x1.x, x1.y, x1.z, x1.w};
#pragma unroll
            for (int r = 0; r < 8; r++) {
                acc[r][0] += xv[r] * wv.x; acc[r][1] += xv[r] * wv.y;
                acc[r][2] += xv[r] * wv.z; acc[r][3] += xv[r] * wv.w;
            }
        }
        __syncthreads();
    }
#pragma unroll
    for (int r = 0; r < 8; r++) {
        int m = row0 + r0 + r;
        if (m < M) {
            __half2 h0 = __floats2half2_rn(acc[r][0], acc[r][1]);
            __half2 h1 = __floats2half2_rn(acc[r][2], acc[r][3]);
            *(uint2*)(out + (size_t)m * 128 + (n0 + c0) / 2) =
                make_uint2(*(unsigned*)&h0, *(unsigned*)&h1);
        }
    }
}

// ---------------- fused alpha + online softmax + aggregation + self-loop ----------
struct Rows { float4 xlA, xlB, eeA, eeB; };

__device__ __forceinline__ float4 h4_to_f4(uint2 u) {
    __half2 h0 = *(__half2*)&u.x, h1 = *(__half2*)&u.y;
    float2 lo = __half22float2(h0), hi = __half22float2(h1);
    return make_float4(lo.x, lo.y, hi.x, hi.y);
}

__device__ __forceinline__ void load_rows(Rows& r, int src, int rel, int lane,
                                          const __half2* __restrict__ reh) {
    const __half2* xlp = g_xlh + (size_t)src * 128;
    const __half2* eep = reh + (size_t)rel * 128;
    r.xlA = h4_to_f4(*(const uint2*)(xlp + 2 * lane));
    r.xlB = h4_to_f4(*(const uint2*)(xlp + 64 + 2 * lane));
    r.eeA = h4_to_f4(*(const uint2*)(eep + 2 * lane));
    r.eeB = h4_to_f4(*(const uint2*)(eep + 64 + 2 * lane));
}

__device__ __forceinline__ void logits(const Rows& r, float4 xrA, float4 xrB,
                                       float4 attA, float4 attB,
                                       float& pA, float& pB) {
    float t;
    t = r.xlA.x + xrA.x + r.eeA.x; t = t > 0.f ? t : 0.2f * t; pA  = t * attA.x;
    t = r.xlA.y + xrA.y + r.eeA.y; t = t > 0.f ? t : 0.2f * t; pA += t * attA.y;
    t = r.xlA.z + xrA.z + r.eeA.z; t = t > 0.f ? t : 0.2f * t; pA += t * attA.z;
    t = r.xlA.w + xrA.w + r.eeA.w; t = t > 0.f ? t : 0.2f * t; pA += t * attA.w;
    t = r.xlB.x + xrB.x + r.eeB.x; t = t > 0.f ? t : 0.2f * t; pB  = t * attB.x;
    t = r.xlB.y + xrB.y + r.eeB.y; t = t > 0.f ? t : 0.2f * t; pB += t * attB.y;
    t = r.xlB.z + xrB.z + r.eeB.z; t = t > 0.f ? t : 0.2f * t; pB += t * attB.z;
    t = r.xlB.w + xrB.w + r.eeB.w; t = t > 0.f ? t : 0.2f * t; pB += t * attB.w;
}

__device__ __forceinline__ void online_update(float pA, float pB, const Rows& r,
                                              float& mA, float& mB, float& sA, float& sB,
                                              float4& accA, float4& accB) {
    float nm = fmaxf(mA, pA);
    float scl = __expf(mA - nm);
    float wgt = __expf(pA - nm);
    sA = sA * scl + wgt;
    accA.x = accA.x * scl + wgt * r.xlA.x;
    accA.y = accA.y * scl + wgt * r.xlA.y;
    accA.z = accA.z * scl + wgt * r.xlA.z;
    accA.w = accA.w * scl + wgt * r.xlA.w;
    mA = nm;
    nm = fmaxf(mB, pB);
    scl = __expf(mB - nm);
    wgt = __expf(pB - nm);
    sB = sB * scl + wgt;
    accB.x = accB.x * scl + wgt * r.xlB.x;
    accB.y = accB.y * scl + wgt * r.xlB.y;
    accB.z = accB.z * scl + wgt * r.xlB.z;
    accB.w = accB.w * scl + wgt * r.xlB.w;
    mB = nm;
}

__global__ __launch_bounds__(256) void k_fused(const float* __restrict__ att,
                                               const float* __restrict__ bias,
                                               float* __restrict__ out,
                                               const __half2* __restrict__ reh) {
    int w = (blockIdx.x * blockDim.x + threadIdx.x) >> 5;
    int lane = threadIdx.x & 31;
    if (w >= NN) return;
    int beg = g_rowptr[w], end = g_rowptr[w + 1];

    float4 attA = *(const float4*)(att + ((lane >> 4) * 64) + (lane & 15) * 4);
    float4 attB = *(const float4*)(att + 128 + ((lane >> 4) * 64) + (lane & 15) * 4);

    const float* xrp = g_xr + (size_t)w * HC;
    float4 xrA = *(const float4*)(xrp + 4 * lane);
    float4 xrB = *(const float4*)(xrp + 128 + 4 * lane);

    float mA = -CUDART_INF_F, mB = -CUDART_INF_F;
    float sA = 0.f, sB = 0.f;
    float4 accA = make_float4(0.f, 0.f, 0.f, 0.f);
    float4 accB = make_float4(0.f, 0.f, 0.f, 0.f);
    float4 esA = make_float4(0.f, 0.f, 0.f, 0.f);
    float4 esB = make_float4(0.f, 0.f, 0.f, 0.f);

    int i = beg;
    for (; i + 2 <= end; i += 2) {
        int2 sr0 = g_srcrel[i];
        int2 sr1 = g_srcrel[i + 1];
        Rows r0, r1;
        load_rows(r0, sr0.x, sr0.y, lane, reh);
        load_rows(r1, sr1.x, sr1.y, lane, reh);
        esA.x += r0.eeA.x; esA.y += r0.eeA.y; esA.z += r0.eeA.z; esA.w += r0.eeA.w;
        esB.x += r0.eeB.x; esB.y += r0.eeB.y; esB.z += r0.eeB.z; esB.w += r0.eeB.w;
        esA.x += r1.eeA.x; esA.y += r1.eeA.y; esA.z += r1.eeA.z; esA.w += r1.eeA.w;
        esB.x += r1.eeB.x; esB.y += r1.eeB.y; esB.z += r1.eeB.z; esB.w += r1.eeB.w;

        float p0A, p0B, p1A, p1B;
        logits(r0, xrA, xrB, attA, attB, p0A, p0B);
        logits(r1, xrA, xrB, attA, attB, p1A, p1B);
#pragma unroll
        for (int off = 1; off < 16; off <<= 1) {
            p0A += __shfl_xor_sync(0xffffffffu, p0A, off);
            p0B += __shfl_xor_sync(0xffffffffu, p0B, off);
            p1A += __shfl_xor_sync(0xffffffffu, p1A, off);
            p1B += __shfl_xor_sync(0xffffffffu, p1B, off);
        }
        online_update(p0A, p0B, r0, mA, mB, sA, sB, accA, accB);
        online_update(p1A, p1B, r1, mA, mB, sA, sB, accA, accB);
    }
    if (i < end) {
        int2 sr = g_srcrel[i];
        Rows r;
        load_rows(r, sr.x, sr.y, lane, reh);
        esA.x += r.eeA.x; esA.y += r.eeA.y; esA.z += r.eeA.z; esA.w += r.eeA.w;
        esB.x += r.eeB.x; esB.y += r.eeB.y; esB.z += r.eeB.z; esB.w += r.eeB.w;
        float pA, pB;
        logits(r, xrA, xrB, attA, attB, pA, pB);
#pragma unroll
        for (int off = 1; off < 16; off <<= 1) {
            pA += __shfl_xor_sync(0xffffffffu, pA, off);
            pB += __shfl_xor_sync(0xffffffffu, pB, off);
        }
        online_update(pA, pB, r, mA, mB, sA, sB, accA, accB);
    }

    {   // self-loop: ee = mean of incoming ee rows, xl = xl[w]
        int deg = end - beg;
        float inv = 1.f / (float)(deg > 1 ? deg : 1);
        Rows r;
        r.eeA = make_float4(esA.x * inv, esA.y * inv, esA.z * inv, esA.w * inv);
        r.eeB = make_float4(esB.x * inv, esB.y * inv, esB.z * inv, esB.w * inv);
        const __half2* xlp = g_xlh + (size_t)w * 128;
        r.xlA = h4_to_f4(*(const uint2*)(xlp + 2 * lane));
        r.xlB = h4_to_f4(*(const uint2*)(xlp + 64 + 2 * lane));
        float pA, pB;
        logits(r, xrA, xrB, attA, attB, pA, pB);
#pragma unroll
        for (int off = 1; off < 16; off <<= 1) {
            pA += __shfl_xor_sync(0xffffffffu, pA, off);
            pB += __shfl_xor_sync(0xffffffffu, pB, off);
        }
        online_update(pA, pB, r, mA, mB, sA, sB, accA, accB);
    }

    float iA = 1.f / sA, iB = 1.f / sB;
    accA.x *= iA; accA.y *= iA; accA.z *= iA; accA.w *= iA;
    accB.x *= iB; accB.y *= iB; accB.z *= iB; accB.w *= iB;
    accA.x += __shfl_xor_sync(0xffffffffu, accA.x, 16);
    accA.y += __shfl_xor_sync(0xffffffffu, accA.y, 16);
    accA.z += __shfl_xor_sync(0xffffffffu, accA.z, 16);
    accA.w += __shfl_xor_sync(0xffffffffu, accA.w, 16);
    accB.x += __shfl_xor_sync(0xffffffffu, accB.x, 16);
    accB.y += __shfl_xor_sync(0xffffffffu, accB.y, 16);
    accB.z += __shfl_xor_sync(0xffffffffu, accB.z, 16);
    accB.w += __shfl_xor_sync(0xffffffffu, accB.w, 16);
    if (lane < 16) {
        float4 bv = *(const float4*)(bias + 4 * lane);
        float4 o;
        o.x = 0.25f * (accA.x + accB.x) + bv.x;
        o.y = 0.25f * (accA.y + accB.y) + bv.y;
        o.z = 0.25f * (accA.z + accB.z) + bv.z;
        o.w = 0.25f * (accA.w + accB.w) + bv.w;
        *(float4*)(out + (size_t)w * 64 + 4 * lane) = o;
    }
}

// ---------------- host ----------------
extern "C" void kernel_launch(void* const* d_in, const int* in_sizes, int n_in,
                              void* d_out, int out_size) {
    const float* x         = (const float*)d_in[0];
    const int* ei          = (const int*)d_in[1];
    const float* relations = (const float*)d_in[2];
    const int* relidx      = (const int*)d_in[3];
    const float* Wl[2]  = {(const float*)d_in[4],  (const float*)d_in[11]};
    const float* blv[2] = {(const float*)d_in[5],  (const float*)d_in[12]};
    const float* Wr[2]  = {(const float*)d_in[6],  (const float*)d_in[13]};
    const float* brv[2] = {(const float*)d_in[7],  (const float*)d_in[14]};
    const float* We[2]  = {(const float*)d_in[8],  (const float*)d_in[15]};
    const float* att[2] = {(const float*)d_in[9],  (const float*)d_in[16]};
    const float* bo[2]  = {(const float*)d_in[10], (const float*)d_in[17]};

    void *pxlh, *pxr, *pre0, *pre1, *ph1, *pdeg, *pcur;
    cudaGetSymbolAddress(&pxlh, g_xlh);
    cudaGetSymbolAddress(&pxr, g_xr);
    cudaGetSymbolAddress(&pre0, g_reh0);
    cudaGetSymbolAddress(&pre1, g_reh1);
    cudaGetSymbolAddress(&ph1, g_h1);
    cudaGetSymbolAddress(&pdeg, g_deg);
    cudaGetSymbolAddress(&pcur, g_cursor);

    dim3 gtc((NN + 63) / 64, 4, 2);
    dim3 gr((RT + 127) / 128, 4);

    // fork: preprocessing + layer-1 re-projection + relations memcpy on s2,
    // layer-0 GEMMs on the main stream, join before each k_fused.
    cudaStream_t s2;
    cudaStreamCreateWithFlags(&s2, cudaStreamNonBlocking);
    cudaEvent_t eFork, ePre, eB2;
    cudaEventCreateWithFlags(&eFork, cudaEventDisableTiming);
    cudaEventCreateWithFlags(&ePre, cudaEventDisableTiming);
    cudaEventCreateWithFlags(&eB2, cudaEventDisableTiming);

    cudaEventRecord(eFork, 0);
    cudaStreamWaitEvent(s2, eFork, 0);

    // --- branch B (s2): CSR build, then layer-1 re GEMM + relations copy ---
    cudaMemsetAsync(pdeg, 0, NN * sizeof(int), s2);
    cudaMemsetAsync(pcur, 0, NN * sizeof(int), s2);
    k_count<<<(EE + 255) / 256, 256, 0, s2>>>(ei);
    k_scan<<<1, 1024, 0, s2>>>();
    k_scatter<<<(EE + 255) / 256, 256, 0, s2>>>(ei);
    k_sortpack<<<(NN * 32 + 255) / 256, 256, 0, s2>>>(ei, relidx);
    cudaEventRecord(ePre, s2);
    k_gemm_re<<<gr, 256, 0, s2>>>(relations, We[1], (__half2*)pre1, RT);
    if (out_size >= NN * 64 + RT * 64)
        cudaMemcpyAsync((float*)d_out + (size_t)NN * 64, relations,
                        (size_t)RT * 64 * sizeof(float), cudaMemcpyDeviceToDevice, s2);
    cudaEventRecord(eB2, s2);

    // --- branch A (main stream): layer-0 projections ---
    k_gemm_tc<<<gtc, 256>>>(x, Wl[0], blv[0], (__half2*)pxlh,
                            Wr[0], brv[0], (float*)pxr, NN);
    k_gemm_re<<<gr, 256>>>(relations, We[0], (__half2*)pre0, RT);

    // join B's CSR, run layer 0
    cudaStreamWaitEvent(0, ePre, 0);
    k_fused<<<(NN + 7) / 8, 256>>>(att[0], bo[0], (float*)ph1, (const __half2*)pre0);

    // layer 1
    k_gemm_tc<<<gtc, 256>>>((const float*)ph1, Wl[1], blv[1], (__half2*)pxlh,
                            Wr[1], brv[1], (float*)pxr, NN);
    cudaStreamWaitEvent(0, eB2, 0);
    k_fused<<<(NN + 7) / 8, 256>>>(att[1], bo[1], (float*)d_out, (const __half2*)pre1);
}

// round 11
// speedup vs baseline: 1.3184x; 1.0783x over previous
#include <cuda_runtime.h>
#include <cuda_fp16.h>
#include <math_constants.h>

#define NN   20000
#define EE   320000
#define RT   512
#define HC   256      // H*C

// ---------------- scratch (device globals: allocation-free) ----------------
__device__ __half2 g_xlh[NN * 128];   // lin_l(x), fp16
__device__ __half2 g_xrh[NN * 128];   // lin_r(x), fp16 (logits only)
__device__ __half2 g_reh0[RT * 128];  // relations @ We0^T, fp16
__device__ __half2 g_reh1[RT * 128];  // relations @ We1^T, fp16
__device__ float   g_h1[NN * 64];     // layer-0 output
__device__ int     g_deg[NN];
__device__ int     g_rowptr[NN + 1];
__device__ int     g_cursor[NN];
__device__ int     g_csr[EE];
__device__ int2    g_srcrel[EE];      // (src, rel) per sorted CSR slot

// ---------------- CSR build ----------------
__global__ void k_count(const int* __restrict__ ei) {
    int i = blockIdx.x * blockDim.x + threadIdx.x;
    if (i < EE) atomicAdd(&g_deg[ei[EE + i]], 1);
}

__global__ void k_scan() {
    __shared__ int wsum[32];
    __shared__ int carry;
    int tid = threadIdx.x, lane = tid & 31, wid = tid >> 5;
    if (tid == 0) { carry = 0; g_rowptr[0] = 0; }
    __syncthreads();
    for (int base = 0; base < NN; base += 1024) {
        int i = base + tid;
        int x = (i < NN) ? g_deg[i] : 0;
#pragma unroll
        for (int off = 1; off < 32; off <<= 1) {
            int t = __shfl_up_sync(0xffffffffu, x, off);
            if (lane >= off) x += t;
        }
        if (lane == 31) wsum[wid] = x;
        __syncthreads();
        if (wid == 0) {
            int s = wsum[lane];
#pragma unroll
            for (int off = 1; off < 32; off <<= 1) {
                int t = __shfl_up_sync(0xffffffffu, s, off);
                if (lane >= off) s += t;
            }
            wsum[lane] = s;
        }
        __syncthreads();
        int total = wsum[31];
        int prefix = carry + (wid ? wsum[wid - 1] : 0) + x;
        if (i < NN) g_rowptr[i + 1] = prefix;
        __syncthreads();
        if (tid == 0) carry += total;
        __syncthreads();
    }
}

__global__ void k_scatter(const int* __restrict__ ei) {
    int i = blockIdx.x * blockDim.x + threadIdx.x;
    if (i >= EE) return;
    int d = ei[EE + i];
    int pos = atomicAdd(&g_cursor[d], 1);
    g_csr[g_rowptr[d] + pos] = i;
}

// warp-per-node: bitonic sort (64 elems) + parallel (src,rel) pack
__global__ __launch_bounds__(256) void k_sortpack(const int* __restrict__ ei,
                                                  const int* __restrict__ relidx) {
    int w = (blockIdx.x * blockDim.x + threadIdx.x) >> 5;
    int lane = threadIdx.x & 31;
    if (w >= NN) return;
    int beg = g_rowptr[w], end = g_rowptr[w + 1];
    int len = end - beg;

    if (len <= 64) {
        int v0 = (beg + lane < end)      ? g_csr[beg + lane]      : 0x7fffffff;
        int v1 = (beg + 32 + lane < end) ? g_csr[beg + 32 + lane] : 0x7fffffff;
#pragma unroll
        for (int k = 2; k <= 64; k <<= 1) {
#pragma unroll
            for (int d = k >> 1; d > 0; d >>= 1) {
                if (d == 32) {
                    int lo = min(v0, v1), hi = max(v0, v1);
                    v0 = lo; v1 = hi;
                } else {
                    bool lower = ((lane & d) == 0);
                    bool up0 = ((lane & k) == 0);
                    bool up1 = (((lane + 32) & k) == 0);
                    int p0 = __shfl_xor_sync(0xffffffffu, v0, d);
                    int p1 = __shfl_xor_sync(0xffffffffu, v1, d);
                    v0 = (lower == up0) ? min(v0, p0) : max(v0, p0);
                    v1 = (lower == up1) ? min(v1, p1) : max(v1, p1);
                }
            }
        }
        if (lane < len) {
            int e = v0;
            g_srcrel[beg + lane] = make_int2(ei[e], relidx[e]);
        }
        if (32 + lane < len) {
            int e = v1;
            g_srcrel[beg + 32 + lane] = make_int2(ei[e], relidx[e]);
        }
    } else {
        if (lane == 0) {
            for (int i = beg + 1; i < end; i++) {
                int v = g_csr[i];
                int j = i - 1;
                while (j >= beg && g_csr[j] > v) { g_csr[j + 1] = g_csr[j]; j--; }
                g_csr[j + 1] = v;
            }
        }
        __syncwarp();
        for (int i = beg + lane; i < end; i += 32) {
            int e = g_csr[i];
            g_srcrel[i] = make_int2(ei[e], relidx[e]);
        }
    }
}

// ---------------- tf32 helpers ----------------
__device__ __forceinline__ unsigned f2tf32(float f) {
    unsigned u;
    asm("cvt.rna.tf32.f32 %0, %1;" : "=r"(u) : "f"(f));
    return u;
}
__device__ __forceinline__ void mma_tf32(float& c0, float& c1, float& c2, float& c3,
                                         unsigned a0, unsigned a1, unsigned a2, unsigned a3,
                                         unsigned b0, unsigned b1) {
    asm("mma.sync.aligned.m16n8k8.row.col.f32.tf32.tf32.f32 "
        "{%0,%1,%2,%3},{%4,%5,%6,%7},{%8,%9},{%0,%1,%2,%3};"
        : "+f"(c0), "+f"(c1), "+f"(c2), "+f"(c3)
        : "r"(a0), "r"(a1), "r"(a2), "r"(a3), "r"(b0), "r"(b1));
}

// ---- tensor-core GEMM: z=0 -> xl (fp16), z=1 -> xr (fp16) ----
__global__ __launch_bounds__(256) void k_gemm_tc(const float* __restrict__ A,
                                                 const float* __restrict__ W0,
                                                 const float* __restrict__ bias0,
                                                 __half2* __restrict__ outH0,
                                                 const float* __restrict__ W1,
                                                 const float* __restrict__ bias1,
                                                 __half2* __restrict__ outH1, int M) {
    int zsel = blockIdx.z;
    const float* W    = zsel ? W1 : W0;
    const float* bias = zsel ? bias1 : bias0;
    __half2* outH     = zsel ? outH1 : outH0;
    __shared__ unsigned As[64][68];
    __shared__ unsigned Ws[64][68];
    int tid = threadIdx.x;
    int row0 = blockIdx.x * 64, n0 = blockIdx.y * 64;

#pragma unroll
    for (int it = 0; it < 4; it++) {
        int idx = tid + it * 256;
        int r = idx >> 4, k4 = idx & 15;
        int m = row0 + r;
        float4 v = (m < M) ? *(const float4*)(A + (size_t)m * 64 + k4 * 4)
                           : make_float4(0.f, 0.f, 0.f, 0.f);
        As[r][k4 * 4 + 0] = f2tf32(v.x); As[r][k4 * 4 + 1] = f2tf32(v.y);
        As[r][k4 * 4 + 2] = f2tf32(v.z); As[r][k4 * 4 + 3] = f2tf32(v.w);
        float4 wv = *(const float4*)(W + (size_t)(n0 + r) * 64 + k4 * 4);
        Ws[r][k4 * 4 + 0] = f2tf32(wv.x); Ws[r][k4 * 4 + 1] = f2tf32(wv.y);
        Ws[r][k4 * 4 + 2] = f2tf32(wv.z); Ws[r][k4 * 4 + 3] = f2tf32(wv.w);
    }
    __syncthreads();

    int wid = tid >> 5, lane = tid & 31;
    int g = lane >> 2, tig = lane & 3;
    int rbase = (wid & 3) * 16;
    int ncb = (wid >> 2) * 32;
    float acc[4][4] = {};
#pragma unroll
    for (int ks = 0; ks < 8; ks++) {
        int k0 = ks * 8;
        unsigned a0 = As[rbase + g][k0 + tig];
        unsigned a1 = As[rbase + g + 8][k0 + tig];
        unsigned a2 = As[rbase + g][k0 + tig + 4];
        unsigned a3 = As[rbase + g + 8][k0 + tig + 4];
#pragma unroll
        for (int nt = 0; nt < 4; nt++) {
            unsigned b0 = Ws[ncb + nt * 8 + g][k0 + tig];
            unsigned b1 = Ws[ncb + nt * 8 + g][k0 + tig + 4];
            mma_tf32(acc[nt][0], acc[nt][1], acc[nt][2], acc[nt][3],
                     a0, a1, a2, a3, b0, b1);
        }
    }
    int m0 = row0 + rbase + g;
#pragma unroll
    for (int nt = 0; nt < 4; nt++) {
        int gcol = n0 + ncb + nt * 8 + tig * 2;
        float2 bv = *(const float2*)(bias + gcol);
        if (m0 < M)
            outH[(size_t)m0 * 128 + gcol / 2] =
                __floats2half2_rn(acc[nt][0] + bv.x, acc[nt][1] + bv.y);
        if (m0 + 8 < M)
            outH[(size_t)(m0 + 8) * 128 + gcol / 2] =
                __floats2half2_rn(acc[nt][2] + bv.x, acc[nt][3] + bv.y);
    }
}

// ---- scalar fp32 GEMM -> fp16 output (relations @ We^T) ----
__global__ __launch_bounds__(256) void k_gemm_re(const float* __restrict__ A,
                                                 const float* __restrict__ W,
                                                 __half2* __restrict__ out, int M) {
    __shared__ float xsT[32][132];
    __shared__ float Ws[32][68];
    int tid = threadIdx.x;
    int row0 = blockIdx.x * 128, n0 = blockIdx.y * 64;
    int rg = tid >> 4, cg = tid & 15;
    int r0 = rg * 8, c0 = cg * 4;
    float acc[8][4] = {};

    for (int kc = 0; kc < 64; kc += 32) {
#pragma unroll
        for (int it = 0; it < 4; ++it) {
            int idx = tid + it * 256;
            int r = idx >> 3, k4 = idx & 7;
            int m = row0 + r;
            float4 v = (m < M) ? *(const float4*)(A + (size_t)m * 64 + kc + k4 * 4)
                               : make_float4(0.f, 0.f, 0.f, 0.f);
            xsT[k4 * 4 + 0][r] = v.x; xsT[k4 * 4 + 1][r] = v.y;
            xsT[k4 * 4 + 2][r] = v.z; xsT[k4 * 4 + 3][r] = v.w;
        }
#pragma unroll
        for (int it = 0; it < 2; ++it) {
            int idx = tid + it * 256;
            int n = idx >> 3, k4 = idx & 7;
            float4 v = *(const float4*)(W + (size_t)(n0 + n) * 64 + kc + k4 * 4);
            Ws[k4 * 4 + 0][n] = v.x; Ws[k4 * 4 + 1][n] = v.y;
            Ws[k4 * 4 + 2][n] = v.z; Ws[k4 * 4 + 3][n] = v.w;
        }
        __syncthreads();
#pragma unroll
        for (int k = 0; k < 32; k++) {
            float4 x0 = *(const float4*)&xsT[k][r0];
            float4 x1 = *(const float4*)&xsT[k][r0 + 4];
            float4 wv = *(const float4*)&Ws[k][c0];
            float xv[8] = {x0.x, x0.y, x0.z, x0.w, x1.x, x1.y, x1.z, x1.w};
#pragma unroll
            for (int r = 0; r < 8; r++) {
                acc[r][0] += xv[r] * wv.x; acc[r][1] += xv[r] * wv.y;
                acc[r][2] += xv[r] * wv.z; acc[r][3] += xv[r] * wv.w;
            }
        }
        __syncthreads();
    }
#pragma unroll
    for (int r = 0; r < 8; r++) {
        int m = row0 + r0 + r;
        if (m < M) {
            __half2 h0 = __floats2half2_rn(acc[r][0], acc[r][1]);
            __half2 h1 = __floats2half2_rn(acc[r][2], acc[r][3]);
            *(uint2*)(out + (size_t)m * 128 + (n0 + c0) / 2) =
                make_uint2(*(unsigned*)&h0, *(unsigned*)&h1);
        }
    }
}

// ---------------- fused: half2 logit arithmetic, fp32 softmax/payload ----------
__device__ __forceinline__ float4 h4_to_f4(uint2 u) {
    __half2 h0 = *(__half2*)&u.x, h1 = *(__half2*)&u.y;
    float2 lo = __half22float2(h0), hi = __half22float2(h1);
    return make_float4(lo.x, lo.y, hi.x, hi.y);
}
__device__ __forceinline__ __half2 u2h(unsigned u) { return *(__half2*)&u; }

struct EdgeU { uint2 xla, xlb, eea, eeb; };

__device__ __forceinline__ void load_edge(EdgeU& e, int src, int rel, int lane,
                                          const __half2* __restrict__ reh) {
    const __half2* xlp = g_xlh + (size_t)src * 128;
    const __half2* eep = reh + (size_t)rel * 128;
    e.xla = *(const uint2*)(xlp + 2 * lane);
    e.xlb = *(const uint2*)(xlp + 64 + 2 * lane);
    e.eea = *(const uint2*)(eep + 2 * lane);
    e.eeb = *(const uint2*)(eep + 64 + 2 * lane);
}

__device__ __forceinline__ float2 logit_h2(const EdgeU& e,
    __half2 xrA0, __half2 xrA1, __half2 xrB0, __half2 xrB1,
    __half2 attA0, __half2 attA1, __half2 attB0, __half2 attB1, __half2 c02) {
    __half2 t, pa, pb;
    t = __hadd2(__hadd2(u2h(e.xla.x), xrA0), u2h(e.eea.x));
    t = __hmax2(t, __hmul2(t, c02));
    pa = __hmul2(t, attA0);
    t = __hadd2(__hadd2(u2h(e.xla.y), xrA1), u2h(e.eea.y));
    t = __hmax2(t, __hmul2(t, c02));
    pa = __hfma2(t, attA1, pa);
    t = __hadd2(__hadd2(u2h(e.xlb.x), xrB0), u2h(e.eeb.x));
    t = __hmax2(t, __hmul2(t, c02));
    pb = __hmul2(t, attB0);
    t = __hadd2(__hadd2(u2h(e.xlb.y), xrB1), u2h(e.eeb.y));
    t = __hmax2(t, __hmul2(t, c02));
    pb = __hfma2(t, attB1, pb);
    float2 fa = __half22float2(pa), fb = __half22float2(pb);
    return make_float2(fa.x + fa.y, fb.x + fb.y);
}

__device__ __forceinline__ void upd(float p, float& m, float& s, float4& acc, float4 xl) {
    float nm = fmaxf(m, p);
    float scl = __expf(m - nm);
    float wgt = __expf(p - nm);
    s = s * scl + wgt;
    acc.x = acc.x * scl + wgt * xl.x;
    acc.y = acc.y * scl + wgt * xl.y;
    acc.z = acc.z * scl + wgt * xl.z;
    acc.w = acc.w * scl + wgt * xl.w;
    m = nm;
}

__global__ __launch_bounds__(256) void k_fused(const float* __restrict__ att,
                                               const float* __restrict__ bias,
                                               float* __restrict__ out,
                                               const __half2* __restrict__ reh) {
    int w = (blockIdx.x * blockDim.x + threadIdx.x) >> 5;
    int lane = threadIdx.x & 31;
    if (w >= NN) return;
    int beg = g_rowptr[w], end = g_rowptr[w + 1];

    float4 attAf = *(const float4*)(att + ((lane >> 4) * 64) + (lane & 15) * 4);
    float4 attBf = *(const float4*)(att + 128 + ((lane >> 4) * 64) + (lane & 15) * 4);
    __half2 attA0 = __floats2half2_rn(attAf.x, attAf.y);
    __half2 attA1 = __floats2half2_rn(attAf.z, attAf.w);
    __half2 attB0 = __floats2half2_rn(attBf.x, attBf.y);
    __half2 attB1 = __floats2half2_rn(attBf.z, attBf.w);

    const __half2* xrp = g_xrh + (size_t)w * 128;
    uint2 xru_a = *(const uint2*)(xrp + 2 * lane);
    uint2 xru_b = *(const uint2*)(xrp + 64 + 2 * lane);
    __half2 xrA0 = u2h(xru_a.x), xrA1 = u2h(xru_a.y);
    __half2 xrB0 = u2h(xru_b.x), xrB1 = u2h(xru_b.y);
    float4 xrAf = h4_to_f4(xru_a), xrBf = h4_to_f4(xru_b);

    const __half2 c02 = __float2half2_rn(0.2f);
    const __half2 hz = __float2half2_rn(0.f);
    __half2 esA0 = hz, esA1 = hz, esB0 = hz, esB1 = hz;

    float mA = -CUDART_INF_F, mB = -CUDART_INF_F;
    float sA = 0.f, sB = 0.f;
    float4 accA = make_float4(0.f, 0.f, 0.f, 0.f);
    float4 accB = make_float4(0.f, 0.f, 0.f, 0.f);

    int i = beg;
    for (; i + 2 <= end; i += 2) {
        int2 sr0 = g_srcrel[i];
        int2 sr1 = g_srcrel[i + 1];
        EdgeU e0, e1;
        load_edge(e0, sr0.x, sr0.y, lane, reh);
        load_edge(e1, sr1.x, sr1.y, lane, reh);
        esA0 = __hadd2(esA0, u2h(e0.eea.x)); esA1 = __hadd2(esA1, u2h(e0.eea.y));
        esB0 = __hadd2(esB0, u2h(e0.eeb.x)); esB1 = __hadd2(esB1, u2h(e0.eeb.y));
        esA0 = __hadd2(esA0, u2h(e1.eea.x)); esA1 = __hadd2(esA1, u2h(e1.eea.y));
        esB0 = __hadd2(esB0, u2h(e1.eeb.x)); esB1 = __hadd2(esB1, u2h(e1.eeb.y));

        float2 p0 = logit_h2(e0, xrA0, xrA1, xrB0, xrB1, attA0, attA1, attB0, attB1, c02);
        float2 p1 = logit_h2(e1, xrA0, xrA1, xrB0, xrB1, attA0, attA1, attB0, attB1, c02);
#pragma unroll
        for (int off = 1; off < 16; off <<= 1) {
            p0.x += __shfl_xor_sync(0xffffffffu, p0.x, off);
            p0.y += __shfl_xor_sync(0xffffffffu, p0.y, off);
            p1.x += __shfl_xor_sync(0xffffffffu, p1.x, off);
            p1.y += __shfl_xor_sync(0xffffffffu, p1.y, off);
        }
        float4 xl0A = h4_to_f4(e0.xla), xl0B = h4_to_f4(e0.xlb);
        float4 xl1A = h4_to_f4(e1.xla), xl1B = h4_to_f4(e1.xlb);
        upd(p0.x, mA, sA, accA, xl0A);
        upd(p0.y, mB, sB, accB, xl0B);
        upd(p1.x, mA, sA, accA, xl1A);
        upd(p1.y, mB, sB, accB, xl1B);
    }
    if (i < end) {
        int2 sr = g_srcrel[i];
        EdgeU e;
        load_edge(e, sr.x, sr.y, lane, reh);
        esA0 = __hadd2(esA0, u2h(e.eea.x)); esA1 = __hadd2(esA1, u2h(e.eea.y));
        esB0 = __hadd2(esB0, u2h(e.eeb.x)); esB1 = __hadd2(esB1, u2h(e.eeb.y));
        float2 p = logit_h2(e, xrA0, xrA1, xrB0, xrB1, attA0, attA1, attB0, attB1, c02);
#pragma unroll
        for (int off = 1; off < 16; off <<= 1) {
            p.x += __shfl_xor_sync(0xffffffffu, p.x, off);
            p.y += __shfl_xor_sync(0xffffffffu, p.y, off);
        }
        float4 xlA = h4_to_f4(e.xla), xlB = h4_to_f4(e.xlb);
        upd(p.x, mA, sA, accA, xlA);
        upd(p.y, mB, sB, accB, xlB);
    }

    {   // self-loop in fp32: ee = mean of incoming ee rows, xl = xl[w]
        int deg = end - beg;
        float inv = 1.f / (float)(deg > 1 ? deg : 1);
        float2 a0 = __half22float2(esA0), a1 = __half22float2(esA1);
        float2 b0 = __half22float2(esB0), b1 = __half22float2(esB1);
        float4 eeA = make_float4(a0.x * inv, a0.y * inv, a1.x * inv, a1.y * inv);
        float4 eeB = make_float4(b0.x * inv, b0.y * inv, b1.x * inv, b1.y * inv);
        const __half2* xlp = g_xlh + (size_t)w * 128;
        uint2 xua = *(const uint2*)(xlp + 2 * lane);
        uint2 xub = *(const uint2*)(xlp + 64 + 2 * lane);
        float4 xlA = h4_to_f4(xua), xlB = h4_to_f4(xub);
        float t, pA, pB;
        t = xlA.x + xrAf.x + eeA.x; t = t > 0.f ? t : 0.2f * t; pA  = t * attAf.x;
        t = xlA.y + xrAf.y + eeA.y; t = t > 0.f ? t : 0.2f * t; pA += t * attAf.y;
        t = xlA.z + xrAf.z + eeA.z; t = t > 0.f ? t : 0.2f * t; pA += t * attAf.z;
        t = xlA.w + xrAf.w + eeA.w; t = t > 0.f ? t : 0.2f * t; pA += t * attAf.w;
        t = xlB.x + xrBf.x + eeB.x; t = t > 0.f ? t : 0.2f * t; pB  = t * attBf.x;
        t = xlB.y + xrBf.y + eeB.y; t = t > 0.f ? t : 0.2f * t; pB += t * attBf.y;
        t = xlB.z + xrBf.z + eeB.z; t = t > 0.f ? t : 0.2f * t; pB += t * attBf.z;
        t = xlB.w + xrBf.w + eeB.w; t = t > 0.f ? t : 0.2f * t; pB += t * attBf.w;
#pragma unroll
        for (int off = 1; off < 16; off <<= 1) {
            pA += __shfl_xor_sync(0xffffffffu, pA, off);
            pB += __shfl_xor_sync(0xffffffffu, pB, off);
        }
        upd(pA, mA, sA, accA, xlA);
        upd(pB, mB, sB, accB, xlB);
    }

    float iA = 1.f / sA, iB = 1.f / sB;
    accA.x *= iA; accA.y *= iA; accA.z *= iA; accA.w *= iA;
    accB.x *= iB; accB.y *= iB; accB.z *= iB; accB.w *= iB;
    accA.x += __shfl_xor_sync(0xffffffffu, accA.x, 16);
    accA.y += __shfl_xor_sync(0xffffffffu, accA.y, 16);
    accA.z += __shfl_xor_sync(0xffffffffu, accA.z, 16);
    accA.w += __shfl_xor_sync(0xffffffffu, accA.w, 16);
    accB.x += __shfl_xor_sync(0xffffffffu, accB.x, 16);
    accB.y += __shfl_xor_sync(0xffffffffu, accB.y, 16);
    accB.z += __shfl_xor_sync(0xffffffffu, accB.z, 16);
    accB.w += __shfl_xor_sync(0xffffffffu, accB.w, 16);
    if (lane < 16) {
        float4 bv = *(const float4*)(bias + 4 * lane);
        float4 o;
        o.x = 0.25f * (accA.x + accB.x) + bv.x;
        o.y = 0.25f * (accA.y + accB.y) + bv.y;
        o.z = 0.25f * (accA.z + accB.z) + bv.z;
        o.w = 0.25f * (accA.w + accB.w) + bv.w;
        *(float4*)(out + (size_t)w * 64 + 4 * lane) = o;
    }
}

// ---------------- host ----------------
extern "C" void kernel_launch(void* const* d_in, const int* in_sizes, int n_in,
                              void* d_out, int out_size) {
    const float* x         = (const float*)d_in[0];
    const int* ei          = (const int*)d_in[1];
    const float* relations = (const float*)d_in[2];
    const int* relidx      = (const int*)d_in[3];
    const float* Wl[2]  = {(const float*)d_in[4],  (const float*)d_in[11]};
    const float* blv[2] = {(const float*)d_in[5],  (const float*)d_in[12]};
    const float* Wr[2]  = {(const float*)d_in[6],  (const float*)d_in[13]};
    const float* brv[2] = {(const float*)d_in[7],  (const float*)d_in[14]};
    const float* We[2]  = {(const float*)d_in[8],  (const float*)d_in[15]};
    const float* att[2] = {(const float*)d_in[9],  (const float*)d_in[16]};
    const float* bo[2]  = {(const float*)d_in[10], (const float*)d_in[17]};

    void *pxlh, *pxrh, *pre0, *pre1, *ph1, *pdeg, *pcur;
    cudaGetSymbolAddress(&pxlh, g_xlh);
    cudaGetSymbolAddress(&pxrh, g_xrh);
    cudaGetSymbolAddress(&pre0, g_reh0);
    cudaGetSymbolAddress(&pre1, g_reh1);
    cudaGetSymbolAddress(&ph1, g_h1);
    cudaGetSymbolAddress(&pdeg, g_deg);
    cudaGetSymbolAddress(&pcur, g_cursor);

    dim3 gtc((NN + 63) / 64, 4, 2);
    dim3 gr((RT + 127) / 128, 4);

    cudaStream_t s2;
    cudaStreamCreateWithFlags(&s2, cudaStreamNonBlocking);
    cudaEvent_t eFork, ePre, eB2;
    cudaEventCreateWithFlags(&eFork, cudaEventDisableTiming);
    cudaEventCreateWithFlags(&ePre, cudaEventDisableTiming);
    cudaEventCreateWithFlags(&eB2, cudaEventDisableTiming);

    cudaEventRecord(eFork, 0);
    cudaStreamWaitEvent(s2, eFork, 0);

    // --- branch B (s2): CSR build, then layer-1 re GEMM + relations copy ---
    cudaMemsetAsync(pdeg, 0, NN * sizeof(int), s2);
    cudaMemsetAsync(pcur, 0, NN * sizeof(int), s2);
    k_count<<<(EE + 255) / 256, 256, 0, s2>>>(ei);
    k_scan<<<1, 1024, 0, s2>>>();
    k_scatter<<<(EE + 255) / 256, 256, 0, s2>>>(ei);
    k_sortpack<<<(NN * 32 + 255) / 256, 256, 0, s2>>>(ei, relidx);
    cudaEventRecord(ePre, s2);
    k_gemm_re<<<gr, 256, 0, s2>>>(relations, We[1], (__half2*)pre1, RT);
    if (out_size >= NN * 64 + RT * 64)
        cudaMemcpyAsync((float*)d_out + (size_t)NN * 64, relations,
                        (size_t)RT * 64 * sizeof(float), cudaMemcpyDeviceToDevice, s2);
    cudaEventRecord(eB2, s2);

    // --- branch A (main stream): layer-0 projections ---
    k_gemm_tc<<<gtc, 256>>>(x, Wl[0], blv[0], (__half2*)pxlh,
                            Wr[0], brv[0], (__half2*)pxrh, NN);
    k_gemm_re<<<gr, 256>>>(relations, We[0], (__half2*)pre0, RT);

    cudaStreamWaitEvent(0, ePre, 0);
    k_fused<<<(NN + 7) / 8, 256>>>(att[0], bo[0], (float*)ph1, (const __half2*)pre0);

    // layer 1
    k_gemm_tc<<<gtc, 256>>>((const float*)ph1, Wl[1], blv[1], (__half2*)pxlh,
                            Wr[1], brv[1], (__half2*)pxrh, NN);
    cudaStreamWaitEvent(0, eB2, 0);
    k_fused<<<(NN + 7) / 8, 256>>>(att[1], bo[1], (float*)d_out, (const __half2*)pre1);
}

// round 12
// speedup vs baseline: 1.3945x; 1.0577x over previous
#include <cuda_runtime.h>
#include <cuda_fp16.h>
#include <math_constants.h>

#define NN   20000
#define EE   320000
#define RT   512
#define HC   256      // H*C

// ---------------- scratch (device globals: allocation-free) ----------------
__device__ __half2 g_xlh[NN * 128];   // lin_l(x), fp16
__device__ __half2 g_xrh[NN * 128];   // lin_r(x), fp16 (logits only)
__device__ __half2 g_reh0[RT * 128];  // relations @ We0^T, fp16
__device__ __half2 g_reh1[RT * 128];  // relations @ We1^T, fp16
__device__ float   g_h1[NN * 64];     // layer-0 output
__device__ int     g_deg[NN];
__device__ int     g_rowptr[NN + 1];
__device__ int     g_cursor[NN];
__device__ int     g_csr[EE];
__device__ int2    g_srcrel[EE];      // (src, rel) per sorted CSR slot

// ---------------- CSR build ----------------
__global__ void k_count(const int* __restrict__ ei) {
    int i = blockIdx.x * blockDim.x + threadIdx.x;
    if (i < EE) atomicAdd(&g_deg[ei[EE + i]], 1);
}

__global__ void k_scan() {
    __shared__ int wsum[32];
    __shared__ int carry;
    int tid = threadIdx.x, lane = tid & 31, wid = tid >> 5;
    if (tid == 0) { carry = 0; g_rowptr[0] = 0; }
    __syncthreads();
    for (int base = 0; base < NN; base += 1024) {
        int i = base + tid;
        int x = (i < NN) ? g_deg[i] : 0;
#pragma unroll
        for (int off = 1; off < 32; off <<= 1) {
            int t = __shfl_up_sync(0xffffffffu, x, off);
            if (lane >= off) x += t;
        }
        if (lane == 31) wsum[wid] = x;
        __syncthreads();
        if (wid == 0) {
            int s = wsum[lane];
#pragma unroll
            for (int off = 1; off < 32; off <<= 1) {
                int t = __shfl_up_sync(0xffffffffu, s, off);
                if (lane >= off) s += t;
            }
            wsum[lane] = s;
        }
        __syncthreads();
        int total = wsum[31];
        int prefix = carry + (wid ? wsum[wid - 1] : 0) + x;
        if (i < NN) g_rowptr[i + 1] = prefix;
        __syncthreads();
        if (tid == 0) carry += total;
        __syncthreads();
    }
}

__global__ void k_scatter(const int* __restrict__ ei) {
    int i = blockIdx.x * blockDim.x + threadIdx.x;
    if (i >= EE) return;
    int d = ei[EE + i];
    int pos = atomicAdd(&g_cursor[d], 1);
    g_csr[g_rowptr[d] + pos] = i;
}

// warp-per-node: bitonic sort (64 elems) + parallel (src,rel) pack
__global__ __launch_bounds__(256) void k_sortpack(const int* __restrict__ ei,
                                                  const int* __restrict__ relidx) {
    int w = (blockIdx.x * blockDim.x + threadIdx.x) >> 5;
    int lane = threadIdx.x & 31;
    if (w >= NN) return;
    int beg = g_rowptr[w], end = g_rowptr[w + 1];
    int len = end - beg;

    if (len <= 64) {
        int v0 = (beg + lane < end)      ? g_csr[beg + lane]      : 0x7fffffff;
        int v1 = (beg + 32 + lane < end) ? g_csr[beg + 32 + lane] : 0x7fffffff;
#pragma unroll
        for (int k = 2; k <= 64; k <<= 1) {
#pragma unroll
            for (int d = k >> 1; d > 0; d >>= 1) {
                if (d == 32) {
                    int lo = min(v0, v1), hi = max(v0, v1);
                    v0 = lo; v1 = hi;
                } else {
                    bool lower = ((lane & d) == 0);
                    bool up0 = ((lane & k) == 0);
                    bool up1 = (((lane + 32) & k) == 0);
                    int p0 = __shfl_xor_sync(0xffffffffu, v0, d);
                    int p1 = __shfl_xor_sync(0xffffffffu, v1, d);
                    v0 = (lower == up0) ? min(v0, p0) : max(v0, p0);
                    v1 = (lower == up1) ? min(v1, p1) : max(v1, p1);
                }
            }
        }
        if (lane < len) {
            int e = v0;
            g_srcrel[beg + lane] = make_int2(ei[e], relidx[e]);
        }
        if (32 + lane < len) {
            int e = v1;
            g_srcrel[beg + 32 + lane] = make_int2(ei[e], relidx[e]);
        }
    } else {
        if (lane == 0) {
            for (int i = beg + 1; i < end; i++) {
                int v = g_csr[i];
                int j = i - 1;
                while (j >= beg && g_csr[j] > v) { g_csr[j + 1] = g_csr[j]; j--; }
                g_csr[j + 1] = v;
            }
        }
        __syncwarp();
        for (int i = beg + lane; i < end; i += 32) {
            int e = g_csr[i];
            g_srcrel[i] = make_int2(ei[e], relidx[e]);
        }
    }
}

// ---------------- tf32 helpers ----------------
__device__ __forceinline__ unsigned f2tf32(float f) {
    unsigned u;
    asm("cvt.rna.tf32.f32 %0, %1;" : "=r"(u) : "f"(f));
    return u;
}
__device__ __forceinline__ void mma_tf32(float& c0, float& c1, float& c2, float& c3,
                                         unsigned a0, unsigned a1, unsigned a2, unsigned a3,
                                         unsigned b0, unsigned b1) {
    asm("mma.sync.aligned.m16n8k8.row.col.f32.tf32.tf32.f32 "
        "{%0,%1,%2,%3},{%4,%5,%6,%7},{%8,%9},{%0,%1,%2,%3};"
        : "+f"(c0), "+f"(c1), "+f"(c2), "+f"(c3)
        : "r"(a0), "r"(a1), "r"(a2), "r"(a3), "r"(b0), "r"(b1));
}

// ---- tensor-core GEMM: z=0 -> xl (fp16), z=1 -> xr (fp16) ----
__global__ __launch_bounds__(256) void k_gemm_tc(const float* __restrict__ A,
                                                 const float* __restrict__ W0,
                                                 const float* __restrict__ bias0,
                                                 __half2* __restrict__ outH0,
                                                 const float* __restrict__ W1,
                                                 const float* __restrict__ bias1,
                                                 __half2* __restrict__ outH1, int M) {
    int zsel = blockIdx.z;
    const float* W    = zsel ? W1 : W0;
    const float* bias = zsel ? bias1 : bias0;
    __half2* outH     = zsel ? outH1 : outH0;
    __shared__ unsigned As[64][68];
    __shared__ unsigned Ws[64][68];
    int tid = threadIdx.x;
    int row0 = blockIdx.x * 64, n0 = blockIdx.y * 64;

#pragma unroll
    for (int it = 0; it < 4; it++) {
        int idx = tid + it * 256;
        int r = idx >> 4, k4 = idx & 15;
        int m = row0 + r;
        float4 v = (m < M) ? *(const float4*)(A + (size_t)m * 64 + k4 * 4)
                           : make_float4(0.f, 0.f, 0.f, 0.f);
        As[r][k4 * 4 + 0] = f2tf32(v.x); As[r][k4 * 4 + 1] = f2tf32(v.y);
        As[r][k4 * 4 + 2] = f2tf32(v.z); As[r][k4 * 4 + 3] = f2tf32(v.w);
        float4 wv = *(const float4*)(W + (size_t)(n0 + r) * 64 + k4 * 4);
        Ws[r][k4 * 4 + 0] = f2tf32(wv.x); Ws[r][k4 * 4 + 1] = f2tf32(wv.y);
        Ws[r][k4 * 4 + 2] = f2tf32(wv.z); Ws[r][k4 * 4 + 3] = f2tf32(wv.w);
    }
    __syncthreads();

    int wid = tid >> 5, lane = tid & 31;
    int g = lane >> 2, tig = lane & 3;
    int rbase = (wid & 3) * 16;
    int ncb = (wid >> 2) * 32;
    float acc[4][4] = {};
#pragma unroll
    for (int ks = 0; ks < 8; ks++) {
        int k0 = ks * 8;
        unsigned a0 = As[rbase + g][k0 + tig];
        unsigned a1 = As[rbase + g + 8][k0 + tig];
        unsigned a2 = As[rbase + g][k0 + tig + 4];
        unsigned a3 = As[rbase + g + 8][k0 + tig + 4];
#pragma unroll
        for (int nt = 0; nt < 4; nt++) {
            unsigned b0 = Ws[ncb + nt * 8 + g][k0 + tig];
            unsigned b1 = Ws[ncb + nt * 8 + g][k0 + tig + 4];
            mma_tf32(acc[nt][0], acc[nt][1], acc[nt][2], acc[nt][3],
                     a0, a1, a2, a3, b0, b1);
        }
    }
    int m0 = row0 + rbase + g;
#pragma unroll
    for (int nt = 0; nt < 4; nt++) {
        int gcol = n0 + ncb + nt * 8 + tig * 2;
        float2 bv = *(const float2*)(bias + gcol);
        if (m0 < M)
            outH[(size_t)m0 * 128 + gcol / 2] =
                __floats2half2_rn(acc[nt][0] + bv.x, acc[nt][1] + bv.y);
        if (m0 + 8 < M)
            outH[(size_t)(m0 + 8) * 128 + gcol / 2] =
                __floats2half2_rn(acc[nt][2] + bv.x, acc[nt][3] + bv.y);
    }
}

// ---- scalar fp32 GEMM -> fp16 output (relations @ We^T) ----
__global__ __launch_bounds__(256) void k_gemm_re(const float* __restrict__ A,
                                                 const float* __restrict__ W,
                                                 __half2* __restrict__ out, int M) {
    __shared__ float xsT[32][132];
    __shared__ float Ws[32][68];
    int tid = threadIdx.x;
    int row0 = blockIdx.x * 128, n0 = blockIdx.y * 64;
    int rg = tid >> 4, cg = tid & 15;
    int r0 = rg * 8, c0 = cg * 4;
    float acc[8][4] = {};

    for (int kc = 0; kc < 64; kc += 32) {
#pragma unroll
        for (int it = 0; it < 4; ++it) {
            int idx = tid + it * 256;
            int r = idx >> 3, k4 = idx & 7;
            int m = row0 + r;
            float4 v = (m < M) ? *(const float4*)(A + (size_t)m * 64 + kc + k4 * 4)
                               : make_float4(0.f, 0.f, 0.f, 0.f);
            xsT[k4 * 4 + 0][r] = v.x; xsT[k4 * 4 + 1][r] = v.y;
            xsT[k4 * 4 + 2][r] = v.z; xsT[k4 * 4 + 3][r] = v.w;
        }
#pragma unroll
        for (int it = 0; it < 2; ++it) {
            int idx = tid + it * 256;
            int n = idx >> 3, k4 = idx & 7;
            float4 v = *(const float4*)(W + (size_t)(n0 + n) * 64 + kc + k4 * 4);
            Ws[k4 * 4 + 0][n] = v.x; Ws[k4 * 4 + 1][n] = v.y;
            Ws[k4 * 4 + 2][n] = v.z; Ws[k4 * 4 + 3][n] = v.w;
        }
        __syncthreads();
#pragma unroll
        for (int k = 0; k < 32; k++) {
            float4 x0 = *(const float4*)&xsT[k][r0];
            float4 x1 = *(const float4*)&xsT[k][r0 + 4];
            float4 wv = *(const float4*)&Ws[k][c0];
            float xv[8] = {x0.x, x0.y, x0.z, x0.w, x1.x, x1.y, x1.z, x1.w};
#pragma unroll
            for (int r = 0; r < 8; r++) {
                acc[r][0] += xv[r] * wv.x; acc[r][1] += xv[r] * wv.y;
                acc[r][2] += xv[r] * wv.z; acc[r][3] += xv[r] * wv.w;
            }
        }
        __syncthreads();
    }
#pragma unroll
    for (int r = 0; r < 8; r++) {
        int m = row0 + r0 + r;
        if (m < M) {
            __half2 h0 = __floats2half2_rn(acc[r][0], acc[r][1]);
            __half2 h1 = __floats2half2_rn(acc[r][2], acc[r][3]);
            *(uint2*)(out + (size_t)m * 128 + (n0 + c0) / 2) =
                make_uint2(*(unsigned*)&h0, *(unsigned*)&h1);
        }
    }
}

// ---------------- fused: half2 logits, max-free softmax (logits are O(1)) ------
__device__ __forceinline__ float4 h4_to_f4(uint2 u) {
    __half2 h0 = *(__half2*)&u.x, h1 = *(__half2*)&u.y;
    float2 lo = __half22float2(h0), hi = __half22float2(h1);
    return make_float4(lo.x, lo.y, hi.x, hi.y);
}
__device__ __forceinline__ __half2 u2h(unsigned u) { return *(__half2*)&u; }

struct EdgeU { uint2 xla, xlb, eea, eeb; };

__device__ __forceinline__ void load_edge(EdgeU& e, int src, int rel, int lane,
                                          const __half2* __restrict__ reh) {
    const __half2* xlp = g_xlh + (size_t)src * 128;
    const __half2* eep = reh + (size_t)rel * 128;
    e.xla = *(const uint2*)(xlp + 2 * lane);
    e.xlb = *(const uint2*)(xlp + 64 + 2 * lane);
    e.eea = *(const uint2*)(eep + 2 * lane);
    e.eeb = *(const uint2*)(eep + 64 + 2 * lane);
}

__device__ __forceinline__ float2 logit_h2(const EdgeU& e,
    __half2 xrA0, __half2 xrA1, __half2 xrB0, __half2 xrB1,
    __half2 attA0, __half2 attA1, __half2 attB0, __half2 attB1, __half2 c02) {
    __half2 t, pa, pb;
    t = __hadd2(__hadd2(u2h(e.xla.x), xrA0), u2h(e.eea.x));
    t = __hmax2(t, __hmul2(t, c02));
    pa = __hmul2(t, attA0);
    t = __hadd2(__hadd2(u2h(e.xla.y), xrA1), u2h(e.eea.y));
    t = __hmax2(t, __hmul2(t, c02));
    pa = __hfma2(t, attA1, pa);
    t = __hadd2(__hadd2(u2h(e.xlb.x), xrB0), u2h(e.eeb.x));
    t = __hmax2(t, __hmul2(t, c02));
    pb = __hmul2(t, attB0);
    t = __hadd2(__hadd2(u2h(e.xlb.y), xrB1), u2h(e.eeb.y));
    t = __hmax2(t, __hmul2(t, c02));
    pb = __hfma2(t, attB1, pb);
    float2 fa = __half22float2(pa), fb = __half22float2(pb);
    return make_float2(fa.x + fa.y, fb.x + fb.y);
}

// max-free softmax accumulate: logits are O(±10), exp is safe in fp32
__device__ __forceinline__ void upd(float p, float& s, float4& acc, float4 xl) {
    float wgt = __expf(p);
    s += wgt;
    acc.x += wgt * xl.x;
    acc.y += wgt * xl.y;
    acc.z += wgt * xl.z;
    acc.w += wgt * xl.w;
}

__global__ __launch_bounds__(256) void k_fused(const float* __restrict__ att,
                                               const float* __restrict__ bias,
                                               float* __restrict__ out,
                                               const __half2* __restrict__ reh) {
    int w = (blockIdx.x * blockDim.x + threadIdx.x) >> 5;
    int lane = threadIdx.x & 31;
    if (w >= NN) return;
    int beg = g_rowptr[w], end = g_rowptr[w + 1];

    float4 attAf = *(const float4*)(att + ((lane >> 4) * 64) + (lane & 15) * 4);
    float4 attBf = *(const float4*)(att + 128 + ((lane >> 4) * 64) + (lane & 15) * 4);
    __half2 attA0 = __floats2half2_rn(attAf.x, attAf.y);
    __half2 attA1 = __floats2half2_rn(attAf.z, attAf.w);
    __half2 attB0 = __floats2half2_rn(attBf.x, attBf.y);
    __half2 attB1 = __floats2half2_rn(attBf.z, attBf.w);

    const __half2* xrp = g_xrh + (size_t)w * 128;
    uint2 xru_a = *(const uint2*)(xrp + 2 * lane);
    uint2 xru_b = *(const uint2*)(xrp + 64 + 2 * lane);
    __half2 xrA0 = u2h(xru_a.x), xrA1 = u2h(xru_a.y);
    __half2 xrB0 = u2h(xru_b.x), xrB1 = u2h(xru_b.y);
    float4 xrAf = h4_to_f4(xru_a), xrBf = h4_to_f4(xru_b);

    const __half2 c02 = __float2half2_rn(0.2f);
    const __half2 hz = __float2half2_rn(0.f);
    __half2 esA0 = hz, esA1 = hz, esB0 = hz, esB1 = hz;

    float sA = 0.f, sB = 0.f;
    float4 accA = make_float4(0.f, 0.f, 0.f, 0.f);
    float4 accB = make_float4(0.f, 0.f, 0.f, 0.f);

    int i = beg;
    for (; i + 2 <= end; i += 2) {
        int2 sr0 = g_srcrel[i];
        int2 sr1 = g_srcrel[i + 1];
        EdgeU e0, e1;
        load_edge(e0, sr0.x, sr0.y, lane, reh);
        load_edge(e1, sr1.x, sr1.y, lane, reh);
        esA0 = __hadd2(esA0, u2h(e0.eea.x)); esA1 = __hadd2(esA1, u2h(e0.eea.y));
        esB0 = __hadd2(esB0, u2h(e0.eeb.x)); esB1 = __hadd2(esB1, u2h(e0.eeb.y));
        esA0 = __hadd2(esA0, u2h(e1.eea.x)); esA1 = __hadd2(esA1, u2h(e1.eea.y));
        esB0 = __hadd2(esB0, u2h(e1.eeb.x)); esB1 = __hadd2(esB1, u2h(e1.eeb.y));

        float2 p0 = logit_h2(e0, xrA0, xrA1, xrB0, xrB1, attA0, attA1, attB0, attB1, c02);
        float2 p1 = logit_h2(e1, xrA0, xrA1, xrB0, xrB1, attA0, attA1, attB0, attB1, c02);
#pragma unroll
        for (int off = 1; off < 16; off <<= 1) {
            p0.x += __shfl_xor_sync(0xffffffffu, p0.x, off);
            p0.y += __shfl_xor_sync(0xffffffffu, p0.y, off);
            p1.x += __shfl_xor_sync(0xffffffffu, p1.x, off);
            p1.y += __shfl_xor_sync(0xffffffffu, p1.y, off);
        }
        float4 xl0A = h4_to_f4(e0.xla), xl0B = h4_to_f4(e0.xlb);
        float4 xl1A = h4_to_f4(e1.xla), xl1B = h4_to_f4(e1.xlb);
        upd(p0.x, sA, accA, xl0A);
        upd(p0.y, sB, accB, xl0B);
        upd(p1.x, sA, accA, xl1A);
        upd(p1.y, sB, accB, xl1B);
    }
    if (i < end) {
        int2 sr = g_srcrel[i];
        EdgeU e;
        load_edge(e, sr.x, sr.y, lane, reh);
        esA0 = __hadd2(esA0, u2h(e.eea.x)); esA1 = __hadd2(esA1, u2h(e.eea.y));
        esB0 = __hadd2(esB0, u2h(e.eeb.x)); esB1 = __hadd2(esB1, u2h(e.eeb.y));
        float2 p = logit_h2(e, xrA0, xrA1, xrB0, xrB1, attA0, attA1, attB0, attB1, c02);
#pragma unroll
        for (int off = 1; off < 16; off <<= 1) {
            p.x += __shfl_xor_sync(0xffffffffu, p.x, off);
            p.y += __shfl_xor_sync(0xffffffffu, p.y, off);
        }
        float4 xlA = h4_to_f4(e.xla), xlB = h4_to_f4(e.xlb);
        upd(p.x, sA, accA, xlA);
        upd(p.y, sB, accB, xlB);
    }

    {   // self-loop in fp32: ee = mean of incoming ee rows, xl = xl[w]
        int deg = end - beg;
        float inv = 1.f / (float)(deg > 1 ? deg : 1);
        float2 a0 = __half22float2(esA0), a1 = __half22float2(esA1);
        float2 b0 = __half22float2(esB0), b1 = __half22float2(esB1);
        float4 eeA = make_float4(a0.x * inv, a0.y * inv, a1.x * inv, a1.y * inv);
        float4 eeB = make_float4(b0.x * inv, b0.y * inv, b1.x * inv, b1.y * inv);
        const __half2* xlp = g_xlh + (size_t)w * 128;
        uint2 xua = *(const uint2*)(xlp + 2 * lane);
        uint2 xub = *(const uint2*)(xlp + 64 + 2 * lane);
        float4 xlA = h4_to_f4(xua), xlB = h4_to_f4(xub);
        float t, pA, pB;
        t = xlA.x + xrAf.x + eeA.x; t = t > 0.f ? t : 0.2f * t; pA  = t * attAf.x;
        t = xlA.y + xrAf.y + eeA.y; t = t > 0.f ? t : 0.2f * t; pA += t * attAf.y;
        t = xlA.z + xrAf.z + eeA.z; t = t > 0.f ? t : 0.2f * t; pA += t * attAf.z;
        t = xlA.w + xrAf.w + eeA.w; t = t > 0.f ? t : 0.2f * t; pA += t * attAf.w;
        t = xlB.x + xrBf.x + eeB.x; t = t > 0.f ? t : 0.2f * t; pB  = t * attBf.x;
        t = xlB.y + xrBf.y + eeB.y; t = t > 0.f ? t : 0.2f * t; pB += t * attBf.y;
        t = xlB.z + xrBf.z + eeB.z; t = t > 0.f ? t : 0.2f * t; pB += t * attBf.z;
        t = xlB.w + xrBf.w + eeB.w; t = t > 0.f ? t : 0.2f * t; pB += t * attBf.w;
#pragma unroll
        for (int off = 1; off < 16; off <<= 1) {
            pA += __shfl_xor_sync(0xffffffffu, pA, off);
            pB += __shfl_xor_sync(0xffffffffu, pB, off);
        }
        upd(pA, sA, accA, xlA);
        upd(pB, sB, accB, xlB);
    }

    float iA = 1.f / sA, iB = 1.f / sB;
    accA.x *= iA; accA.y *= iA; accA.z *= iA; accA.w *= iA;
    accB.x *= iB; accB.y *= iB; accB.z *= iB; accB.w *= iB;
    accA.x += __shfl_xor_sync(0xffffffffu, accA.x, 16);
    accA.y += __shfl_xor_sync(0xffffffffu, accA.y, 16);
    accA.z += __shfl_xor_sync(0xffffffffu, accA.z, 16);
    accA.w += __shfl_xor_sync(0xffffffffu, accA.w, 16);
    accB.x += __shfl_xor_sync(0xffffffffu, accB.x, 16);
    accB.y += __shfl_xor_sync(0xffffffffu, accB.y, 16);
    accB.z += __shfl_xor_sync(0xffffffffu, accB.z, 16);
    accB.w += __shfl_xor_sync(0xffffffffu, accB.w, 16);
    if (lane < 16) {
        float4 bv = *(const float4*)(bias + 4 * lane);
        float4 o;
        o.x = 0.25f * (accA.x + accB.x) + bv.x;
        o.y = 0.25f * (accA.y + accB.y) + bv.y;
        o.z = 0.25f * (accA.z + accB.z) + bv.z;
        o.w = 0.25f * (accA.w + accB.w) + bv.w;
        *(float4*)(out + (size_t)w * 64 + 4 * lane) = o;
    }
}

// ---------------- host ----------------
extern "C" void kernel_launch(void* const* d_in, const int* in_sizes, int n_in,
                              void* d_out, int out_size) {
    const float* x         = (const float*)d_in[0];
    const int* ei          = (const int*)d_in[1];
    const float* relations = (const float*)d_in[2];
    const int* relidx      = (const int*)d_in[3];
    const float* Wl[2]  = {(const float*)d_in[4],  (const float*)d_in[11]};
    const float* blv[2] = {(const float*)d_in[5],  (const float*)d_in[12]};
    const float* Wr[2]  = {(const float*)d_in[6],  (const float*)d_in[13]};
    const float* brv[2] = {(const float*)d_in[7],  (const float*)d_in[14]};
    const float* We[2]  = {(const float*)d_in[8],  (const float*)d_in[15]};
    const float* att[2] = {(const float*)d_in[9],  (const float*)d_in[16]};
    const float* bo[2]  = {(const float*)d_in[10], (const float*)d_in[17]};

    void *pxlh, *pxrh, *pre0, *pre1, *ph1, *pdeg, *pcur;
    cudaGetSymbolAddress(&pxlh, g_xlh);
    cudaGetSymbolAddress(&pxrh, g_xrh);
    cudaGetSymbolAddress(&pre0, g_reh0);
    cudaGetSymbolAddress(&pre1, g_reh1);
    cudaGetSymbolAddress(&ph1, g_h1);
    cudaGetSymbolAddress(&pdeg, g_deg);
    cudaGetSymbolAddress(&pcur, g_cursor);

    dim3 gtc((NN + 63) / 64, 4, 2);
    dim3 gr((RT + 127) / 128, 4);

    cudaStream_t s2;
    cudaStreamCreateWithFlags(&s2, cudaStreamNonBlocking);
    cudaEvent_t eFork, ePre, eB2;
    cudaEventCreateWithFlags(&eFork, cudaEventDisableTiming);
    cudaEventCreateWithFlags(&ePre, cudaEventDisableTiming);
    cudaEventCreateWithFlags(&eB2, cudaEventDisableTiming);

    cudaEventRecord(eFork, 0);
    cudaStreamWaitEvent(s2, eFork, 0);

    // --- branch B (s2): CSR build, then layer-1 re GEMM + relations copy ---
    cudaMemsetAsync(pdeg, 0, NN * sizeof(int), s2);
    cudaMemsetAsync(pcur, 0, NN * sizeof(int), s2);
    k_count<<<(EE + 255) / 256, 256, 0, s2>>>(ei);
    k_scan<<<1, 1024, 0, s2>>>();
    k_scatter<<<(EE + 255) / 256, 256, 0, s2>>>(ei);
    k_sortpack<<<(NN * 32 + 255) / 256, 256, 0, s2>>>(ei, relidx);
    cudaEventRecord(ePre, s2);
    k_gemm_re<<<gr, 256, 0, s2>>>(relations, We[1], (__half2*)pre1, RT);
    if (out_size >= NN * 64 + RT * 64)
        cudaMemcpyAsync((float*)d_out + (size_t)NN * 64, relations,
                        (size_t)RT * 64 * sizeof(float), cudaMemcpyDeviceToDevice, s2);
    cudaEventRecord(eB2, s2);

    // --- branch A (main stream): layer-0 projections ---
    k_gemm_tc<<<gtc, 256>>>(x, Wl[0], blv[0], (__half2*)pxlh,
                            Wr[0], brv[0], (__half2*)pxrh, NN);
    k_gemm_re<<<gr, 256>>>(relations, We[0], (__half2*)pre0, RT);

    cudaStreamWaitEvent(0, ePre, 0);
    k_fused<<<(NN + 7) / 8, 256>>>(att[0], bo[0], (float*)ph1, (const __half2*)pre0);

    // layer 1
    k_gemm_tc<<<gtc, 256>>>((const float*)ph1, Wl[1], blv[1], (__half2*)pxlh,
                            Wr[1], brv[1], (__half2*)pxrh, NN);
    cudaStreamWaitEvent(0, eB2, 0);
    k_fused<<<(NN + 7) / 8, 256>>>(att[1], bo[1], (float*)d_out, (const __half2*)pre1);
}

// round 13
// speedup vs baseline: 1.5065x; 1.0803x over previous
#include <cuda_runtime.h>
#include <cuda_fp16.h>
#include <math_constants.h>

#define NN   20000
#define EE   320000
#define RT   512
#define HC   256      // H*C
#define SCAN_BLOCKS ((NN + 1023) / 1024)   // 20

// ---------------- scratch (device globals: allocation-free) ----------------
__device__ __half2 g_xlh[NN * 128];   // lin_l(x), fp16
__device__ __half2 g_xrh[NN * 128];   // lin_r(x), fp16 (logits only)
__device__ __half2 g_reh0[RT * 128];  // relations @ We0^T, fp16
__device__ __half2 g_reh1[RT * 128];  // relations @ We1^T, fp16
__device__ float   g_h1[NN * 64];     // layer-0 output
__device__ int     g_cnt[2 * NN];     // [0,NN)=deg, [NN,2NN)=cursor (one memset)
__device__ int     g_rowptr[NN + 1];
__device__ int     g_bsum[32];
__device__ int     g_boff[32];
__device__ int     g_csr[EE];
__device__ int2    g_srcrel[EE];      // (src, rel) per sorted CSR slot

// ---------------- CSR build ----------------
__global__ void k_count(const int* __restrict__ ei) {
    int i = blockIdx.x * blockDim.x + threadIdx.x;
    if (i < EE) atomicAdd(&g_cnt[ei[EE + i]], 1);
}

// multi-block scan, phase A: per-block inclusive scan + block sum
__global__ __launch_bounds__(1024) void k_scanA() {
    __shared__ int wsum[32];
    int tid = threadIdx.x, lane = tid & 31, wid = tid >> 5;
    int i = blockIdx.x * 1024 + tid;
    int x = (i < NN) ? g_cnt[i] : 0;
#pragma unroll
    for (int off = 1; off < 32; off <<= 1) {
        int t = __shfl_up_sync(0xffffffffu, x, off);
        if (lane >= off) x += t;
    }
    if (lane == 31) wsum[wid] = x;
    __syncthreads();
    if (wid == 0) {
        int s = wsum[lane];
#pragma unroll
        for (int off = 1; off < 32; off <<= 1) {
            int t = __shfl_up_sync(0xffffffffu, s, off);
            if (lane >= off) s += t;
        }
        wsum[lane] = s;
    }
    __syncthreads();
    int incl = x + (wid ? wsum[wid - 1] : 0);
    if (i < NN) g_rowptr[i + 1] = incl;
    if (tid == 0) g_bsum[blockIdx.x] = wsum[31];
}

// phase B: one warp scans block sums -> exclusive offsets
__global__ void k_scanB() {
    int lane = threadIdx.x;
    int v = (lane < SCAN_BLOCKS) ? g_bsum[lane] : 0;
    int x = v;
#pragma unroll
    for (int off = 1; off < 32; off <<= 1) {
        int t = __shfl_up_sync(0xffffffffu, x, off);
        if (lane >= off) x += t;
    }
    if (lane < SCAN_BLOCKS) g_boff[lane] = x - v;
    if (lane == 0) g_rowptr[0] = 0;
}

// phase C: add block offsets
__global__ __launch_bounds__(1024) void k_scanC() {
    int i = blockIdx.x * 1024 + threadIdx.x;
    if (i < NN) g_rowptr[i + 1] += g_boff[blockIdx.x];
}

__global__ void k_scatter(const int* __restrict__ ei) {
    int i = blockIdx.x * blockDim.x + threadIdx.x;
    if (i >= EE) return;
    int d = ei[EE + i];
    int pos = atomicAdd(&g_cnt[NN + d], 1);
    g_csr[g_rowptr[d] + pos] = i;
}

// warp-per-node: bitonic sort + parallel (src,rel) pack.
// Fast path len<=32 (1 reg), mid path len<=64 (2 regs), serial fallback.
__global__ __launch_bounds__(256) void k_sortpack(const int* __restrict__ ei,
                                                  const int* __restrict__ relidx) {
    int w = (blockIdx.x * blockDim.x + threadIdx.x) >> 5;
    int lane = threadIdx.x & 31;
    if (w >= NN) return;
    int beg = g_rowptr[w], end = g_rowptr[w + 1];
    int len = end - beg;

    if (len <= 32) {
        int v = (lane < len) ? g_csr[beg + lane] : 0x7fffffff;
#pragma unroll
        for (int k = 2; k <= 32; k <<= 1) {
#pragma unroll
            for (int d = k >> 1; d > 0; d >>= 1) {
                int p = __shfl_xor_sync(0xffffffffu, v, d);
                bool lower = ((lane & d) == 0);
                bool up = ((lane & k) == 0);
                v = (lower == up) ? min(v, p) : max(v, p);
            }
        }
        if (lane < len) {
            int e = v;
            g_srcrel[beg + lane] = make_int2(ei[e], relidx[e]);
        }
    } else if (len <= 64) {
        int v0 = (beg + lane < end)      ? g_csr[beg + lane]      : 0x7fffffff;
        int v1 = (beg + 32 + lane < end) ? g_csr[beg + 32 + lane] : 0x7fffffff;
#pragma unroll
        for (int k = 2; k <= 64; k <<= 1) {
#pragma unroll
            for (int d = k >> 1; d > 0; d >>= 1) {
                if (d == 32) {
                    int lo = min(v0, v1), hi = max(v0, v1);
                    v0 = lo; v1 = hi;
                } else {
                    bool lower = ((lane & d) == 0);
                    bool up0 = ((lane & k) == 0);
                    bool up1 = (((lane + 32) & k) == 0);
                    int p0 = __shfl_xor_sync(0xffffffffu, v0, d);
                    int p1 = __shfl_xor_sync(0xffffffffu, v1, d);
                    v0 = (lower == up0) ? min(v0, p0) : max(v0, p0);
                    v1 = (lower == up1) ? min(v1, p1) : max(v1, p1);
                }
            }
        }
        if (lane < len) {
            int e = v0;
            g_srcrel[beg + lane] = make_int2(ei[e], relidx[e]);
        }
        if (32 + lane < len) {
            int e = v1;
            g_srcrel[beg + 32 + lane] = make_int2(ei[e], relidx[e]);
        }
    } else {
        if (lane == 0) {
            for (int i = beg + 1; i < end; i++) {
                int v = g_csr[i];
                int j = i - 1;
                while (j >= beg && g_csr[j] > v) { g_csr[j + 1] = g_csr[j]; j--; }
                g_csr[j + 1] = v;
            }
        }
        __syncwarp();
        for (int i = beg + lane; i < end; i += 32) {
            int e = g_csr[i];
            g_srcrel[i] = make_int2(ei[e], relidx[e]);
        }
    }
}

// ---------------- tf32 helpers ----------------
__device__ __forceinline__ unsigned f2tf32(float f) {
    unsigned u;
    asm("cvt.rna.tf32.f32 %0, %1;" : "=r"(u) : "f"(f));
    return u;
}
__device__ __forceinline__ void mma_tf32(float& c0, float& c1, float& c2, float& c3,
                                         unsigned a0, unsigned a1, unsigned a2, unsigned a3,
                                         unsigned b0, unsigned b1) {
    asm("mma.sync.aligned.m16n8k8.row.col.f32.tf32.tf32.f32 "
        "{%0,%1,%2,%3},{%4,%5,%6,%7},{%8,%9},{%0,%1,%2,%3};"
        : "+f"(c0), "+f"(c1), "+f"(c2), "+f"(c3)
        : "r"(a0), "r"(a1), "r"(a2), "r"(a3), "r"(b0), "r"(b1));
}

// ---- tensor-core GEMM: z=0 -> xl (fp16), z=1 -> xr (fp16) ----
__global__ __launch_bounds__(256) void k_gemm_tc(const float* __restrict__ A,
                                                 const float* __restrict__ W0,
                                                 const float* __restrict__ bias0,
                                                 __half2* __restrict__ outH0,
                                                 const float* __restrict__ W1,
                                                 const float* __restrict__ bias1,
                                                 __half2* __restrict__ outH1, int M) {
    int zsel = blockIdx.z;
    const float* W    = zsel ? W1 : W0;
    const float* bias = zsel ? bias1 : bias0;
    __half2* outH     = zsel ? outH1 : outH0;
    __shared__ unsigned As[64][68];
    __shared__ unsigned Ws[64][68];
    int tid = threadIdx.x;
    int row0 = blockIdx.x * 64, n0 = blockIdx.y * 64;

#pragma unroll
    for (int it = 0; it < 4; it++) {
        int idx = tid + it * 256;
        int r = idx >> 4, k4 = idx & 15;
        int m = row0 + r;
        float4 v = (m < M) ? *(const float4*)(A + (size_t)m * 64 + k4 * 4)
                           : make_float4(0.f, 0.f, 0.f, 0.f);
        As[r][k4 * 4 + 0] = f2tf32(v.x); As[r][k4 * 4 + 1] = f2tf32(v.y);
        As[r][k4 * 4 + 2] = f2tf32(v.z); As[r][k4 * 4 + 3] = f2tf32(v.w);
        float4 wv = *(const float4*)(W + (size_t)(n0 + r) * 64 + k4 * 4);
        Ws[r][k4 * 4 + 0] = f2tf32(wv.x); Ws[r][k4 * 4 + 1] = f2tf32(wv.y);
        Ws[r][k4 * 4 + 2] = f2tf32(wv.z); Ws[r][k4 * 4 + 3] = f2tf32(wv.w);
    }
    __syncthreads();

    int wid = tid >> 5, lane = tid & 31;
    int g = lane >> 2, tig = lane & 3;
    int rbase = (wid & 3) * 16;
    int ncb = (wid >> 2) * 32;
    float acc[4][4] = {};
#pragma unroll
    for (int ks = 0; ks < 8; ks++) {
        int k0 = ks * 8;
        unsigned a0 = As[rbase + g][k0 + tig];
        unsigned a1 = As[rbase + g + 8][k0 + tig];
        unsigned a2 = As[rbase + g][k0 + tig + 4];
        unsigned a3 = As[rbase + g + 8][k0 + tig + 4];
#pragma unroll
        for (int nt = 0; nt < 4; nt++) {
            unsigned b0 = Ws[ncb + nt * 8 + g][k0 + tig];
            unsigned b1 = Ws[ncb + nt * 8 + g][k0 + tig + 4];
            mma_tf32(acc[nt][0], acc[nt][1], acc[nt][2], acc[nt][3],
                     a0, a1, a2, a3, b0, b1);
        }
    }
    int m0 = row0 + rbase + g;
#pragma unroll
    for (int nt = 0; nt < 4; nt++) {
        int gcol = n0 + ncb + nt * 8 + tig * 2;
        float2 bv = *(const float2*)(bias + gcol);
        if (m0 < M)
            outH[(size_t)m0 * 128 + gcol / 2] =
                __floats2half2_rn(acc[nt][0] + bv.x, acc[nt][1] + bv.y);
        if (m0 + 8 < M)
            outH[(size_t)(m0 + 8) * 128 + gcol / 2] =
                __floats2half2_rn(acc[nt][2] + bv.x, acc[nt][3] + bv.y);
    }
}

// ---- scalar fp32 GEMM -> fp16 output (relations @ We^T) ----
__global__ __launch_bounds__(256) void k_gemm_re(const float* __restrict__ A,
                                                 const float* __restrict__ W,
                                                 __half2* __restrict__ out, int M) {
    __shared__ float xsT[32][132];
    __shared__ float Ws[32][68];
    int tid = threadIdx.x;
    int row0 = blockIdx.x * 128, n0 = blockIdx.y * 64;
    int rg = tid >> 4, cg = tid & 15;
    int r0 = rg * 8, c0 = cg * 4;
    float acc[8][4] = {};

    for (int kc = 0; kc < 64; kc += 32) {
#pragma unroll
        for (int it = 0; it < 4; ++it) {
            int idx = tid + it * 256;
            int r = idx >> 3, k4 = idx & 7;
            int m = row0 + r;
            float4 v = (m < M) ? *(const float4*)(A + (size_t)m * 64 + kc + k4 * 4)
                               : make_float4(0.f, 0.f, 0.f, 0.f);
            xsT[k4 * 4 + 0][r] = v.x; xsT[k4 * 4 + 1][r] = v.y;
            xsT[k4 * 4 + 2][r] = v.z; xsT[k4 * 4 + 3][r] = v.w;
        }
#pragma unroll
        for (int it = 0; it < 2; ++it) {
            int idx = tid + it * 256;
            int n = idx >> 3, k4 = idx & 7;
            float4 v = *(const float4*)(W + (size_t)(n0 + n) * 64 + kc + k4 * 4);
            Ws[k4 * 4 + 0][n] = v.x; Ws[k4 * 4 + 1][n] = v.y;
            Ws[k4 * 4 + 2][n] = v.z; Ws[k4 * 4 + 3][n] = v.w;
        }
        __syncthreads();
#pragma unroll
        for (int k = 0; k < 32; k++) {
            float4 x0 = *(const float4*)&xsT[k][r0];
            float4 x1 = *(const float4*)&xsT[k][r0 + 4];
            float4 wv = *(const float4*)&Ws[k][c0];
            float xv[8] = {x0.x, x0.y, x0.z, x0.w, x1.x, x1.y, x1.z, x1.w};
#pragma unroll
            for (int r = 0; r < 8; r++) {
                acc[r][0] += xv[r] * wv.x; acc[r][1] += xv[r] * wv.y;
                acc[r][2] += xv[r] * wv.z; acc[r][3] += xv[r] * wv.w;
            }
        }
        __syncthreads();
    }
#pragma unroll
    for (int r = 0; r < 8; r++) {
        int m = row0 + r0 + r;
        if (m < M) {
            __half2 h0 = __floats2half2_rn(acc[r][0], acc[r][1]);
            __half2 h1 = __floats2half2_rn(acc[r][2], acc[r][3]);
            *(uint2*)(out + (size_t)m * 128 + (n0 + c0) / 2) =
                make_uint2(*(unsigned*)&h0, *(unsigned*)&h1);
        }
    }
}

// ---------------- fused: half2 logits, max-free softmax ----------
__device__ __forceinline__ float4 h4_to_f4(uint2 u) {
    __half2 h0 = *(__half2*)&u.x, h1 = *(__half2*)&u.y;
    float2 lo = __half22float2(h0), hi = __half22float2(h1);
    return make_float4(lo.x, lo.y, hi.x, hi.y);
}
__device__ __forceinline__ __half2 u2h(unsigned u) { return *(__half2*)&u; }

struct EdgeU { uint2 xla, xlb, eea, eeb; };

__device__ __forceinline__ void load_edge(EdgeU& e, int src, int rel, int lane,
                                          const __half2* __restrict__ reh) {
    const __half2* xlp = g_xlh + (size_t)src * 128;
    const __half2* eep = reh + (size_t)rel * 128;
    e.xla = *(const uint2*)(xlp + 2 * lane);
    e.xlb = *(const uint2*)(xlp + 64 + 2 * lane);
    e.eea = *(const uint2*)(eep + 2 * lane);
    e.eeb = *(const uint2*)(eep + 64 + 2 * lane);
}

__device__ __forceinline__ float2 logit_h2(const EdgeU& e,
    __half2 xrA0, __half2 xrA1, __half2 xrB0, __half2 xrB1,
    __half2 attA0, __half2 attA1, __half2 attB0, __half2 attB1, __half2 c02) {
    __half2 t, pa, pb;
    t = __hadd2(__hadd2(u2h(e.xla.x), xrA0), u2h(e.eea.x));
    t = __hmax2(t, __hmul2(t, c02));
    pa = __hmul2(t, attA0);
    t = __hadd2(__hadd2(u2h(e.xla.y), xrA1), u2h(e.eea.y));
    t = __hmax2(t, __hmul2(t, c02));
    pa = __hfma2(t, attA1, pa);
    t = __hadd2(__hadd2(u2h(e.xlb.x), xrB0), u2h(e.eeb.x));
    t = __hmax2(t, __hmul2(t, c02));
    pb = __hmul2(t, attB0);
    t = __hadd2(__hadd2(u2h(e.xlb.y), xrB1), u2h(e.eeb.y));
    t = __hmax2(t, __hmul2(t, c02));
    pb = __hfma2(t, attB1, pb);
    float2 fa = __half22float2(pa), fb = __half22float2(pb);
    return make_float2(fa.x + fa.y, fb.x + fb.y);
}

__device__ __forceinline__ void upd(float p, float& s, float4& acc, float4 xl) {
    float wgt = __expf(p);
    s += wgt;
    acc.x += wgt * xl.x;
    acc.y += wgt * xl.y;
    acc.z += wgt * xl.z;
    acc.w += wgt * xl.w;
}

__global__ __launch_bounds__(256) void k_fused(const float* __restrict__ att,
                                               const float* __restrict__ bias,
                                               float* __restrict__ out,
                                               const __half2* __restrict__ reh) {
    int w = (blockIdx.x * blockDim.x + threadIdx.x) >> 5;
    int lane = threadIdx.x & 31;
    if (w >= NN) return;
    int beg = g_rowptr[w], end = g_rowptr[w + 1];

    float4 attAf = *(const float4*)(att + ((lane >> 4) * 64) + (lane & 15) * 4);
    float4 attBf = *(const float4*)(att + 128 + ((lane >> 4) * 64) + (lane & 15) * 4);
    __half2 attA0 = __floats2half2_rn(attAf.x, attAf.y);
    __half2 attA1 = __floats2half2_rn(attAf.z, attAf.w);
    __half2 attB0 = __floats2half2_rn(attBf.x, attBf.y);
    __half2 attB1 = __floats2half2_rn(attBf.z, attBf.w);

    const __half2* xrp = g_xrh + (size_t)w * 128;
    uint2 xru_a = *(const uint2*)(xrp + 2 * lane);
    uint2 xru_b = *(const uint2*)(xrp + 64 + 2 * lane);
    __half2 xrA0 = u2h(xru_a.x), xrA1 = u2h(xru_a.y);
    __half2 xrB0 = u2h(xru_b.x), xrB1 = u2h(xru_b.y);
    float4 xrAf = h4_to_f4(xru_a), xrBf = h4_to_f4(xru_b);

    const __half2 c02 = __float2half2_rn(0.2f);
    const __half2 hz = __float2half2_rn(0.f);
    __half2 esA0 = hz, esA1 = hz, esB0 = hz, esB1 = hz;

    float sA = 0.f, sB = 0.f;
    float4 accA = make_float4(0.f, 0.f, 0.f, 0.f);
    float4 accB = make_float4(0.f, 0.f, 0.f, 0.f);

    int i = beg;
    for (; i + 2 <= end; i += 2) {
        int2 sr0 = g_srcrel[i];
        int2 sr1 = g_srcrel[i + 1];
        EdgeU e0, e1;
        load_edge(e0, sr0.x, sr0.y, lane, reh);
        load_edge(e1, sr1.x, sr1.y, lane, reh);
        esA0 = __hadd2(esA0, u2h(e0.eea.x)); esA1 = __hadd2(esA1, u2h(e0.eea.y));
        esB0 = __hadd2(esB0, u2h(e0.eeb.x)); esB1 = __hadd2(esB1, u2h(e0.eeb.y));
        esA0 = __hadd2(esA0, u2h(e1.eea.x)); esA1 = __hadd2(esA1, u2h(e1.eea.y));
        esB0 = __hadd2(esB0, u2h(e1.eeb.x)); esB1 = __hadd2(esB1, u2h(e1.eeb.y));

        float2 p0 = logit_h2(e0, xrA0, xrA1, xrB0, xrB1, attA0, attA1, attB0, attB1, c02);
        float2 p1 = logit_h2(e1, xrA0, xrA1, xrB0, xrB1, attA0, attA1, attB0, attB1, c02);
#pragma unroll
        for (int off = 1; off < 16; off <<= 1) {
            p0.x += __shfl_xor_sync(0xffffffffu, p0.x, off);
            p0.y += __shfl_xor_sync(0xffffffffu, p0.y, off);
            p1.x += __shfl_xor_sync(0xffffffffu, p1.x, off);
            p1.y += __shfl_xor_sync(0xffffffffu, p1.y, off);
        }
        float4 xl0A = h4_to_f4(e0.xla), xl0B = h4_to_f4(e0.xlb);
        float4 xl1A = h4_to_f4(e1.xla), xl1B = h4_to_f4(e1.xlb);
        upd(p0.x, sA, accA, xl0A);
        upd(p0.y, sB, accB, xl0B);
        upd(p1.x, sA, accA, xl1A);
        upd(p1.y, sB, accB, xl1B);
    }
    if (i < end) {
        int2 sr = g_srcrel[i];
        EdgeU e;
        load_edge(e, sr.x, sr.y, lane, reh);
        esA0 = __hadd2(esA0, u2h(e.eea.x)); esA1 = __hadd2(esA1, u2h(e.eea.y));
        esB0 = __hadd2(esB0, u2h(e.eeb.x)); esB1 = __hadd2(esB1, u2h(e.eeb.y));
        float2 p = logit_h2(e, xrA0, xrA1, xrB0, xrB1, attA0, attA1, attB0, attB1, c02);
#pragma unroll
        for (int off = 1; off < 16; off <<= 1) {
            p.x += __shfl_xor_sync(0xffffffffu, p.x, off);
            p.y += __shfl_xor_sync(0xffffffffu, p.y, off);
        }
        float4 xlA = h4_to_f4(e.xla), xlB = h4_to_f4(e.xlb);
        upd(p.x, sA, accA, xlA);
        upd(p.y, sB, accB, xlB);
    }

    {   // self-loop in fp32: ee = mean of incoming ee rows, xl = xl[w]
        int deg = end - beg;
        float inv = 1.f / (float)(deg > 1 ? deg : 1);
        float2 a0 = __half22float2(esA0), a1 = __half22float2(esA1);
        float2 b0 = __half22float2(esB0), b1 = __half22float2(esB1);
        float4 eeA = make_float4(a0.x * inv, a0.y * inv, a1.x * inv, a1.y * inv);
        float4 eeB = make_float4(b0.x * inv, b0.y * inv, b1.x * inv, b1.y * inv);
        const __half2* xlp = g_xlh + (size_t)w * 128;
        uint2 xua = *(const uint2*)(xlp + 2 * lane);
        uint2 xub = *(const uint2*)(xlp + 64 + 2 * lane);
        float4 xlA = h4_to_f4(xua), xlB = h4_to_f4(xub);
        float t, pA, pB;
        t = xlA.x + xrAf.x + eeA.x; t = t > 0.f ? t : 0.2f * t; pA  = t * attAf.x;
        t = xlA.y + xrAf.y + eeA.y; t = t > 0.f ? t : 0.2f * t; pA += t * attAf.y;
        t = xlA.z + xrAf.z + eeA.z; t = t > 0.f ? t : 0.2f * t; pA += t * attAf.z;
        t = xlA.w + xrAf.w + eeA.w; t = t > 0.f ? t : 0.2f * t; pA += t * attAf.w;
        t = xlB.x + xrBf.x + eeB.x; t = t > 0.f ? t : 0.2f * t; pB  = t * attBf.x;
        t = xlB.y + xrBf.y + eeB.y; t = t > 0.f ? t : 0.2f * t; pB += t * attBf.y;
        t = xlB.z + xrBf.z + eeB.z; t = t > 0.f ? t : 0.2f * t; pB += t * attBf.z;
        t = xlB.w + xrBf.w + eeB.w; t = t > 0.f ? t : 0.2f * t; pB += t * attBf.w;
#pragma unroll
        for (int off = 1; off < 16; off <<= 1) {
            pA += __shfl_xor_sync(0xffffffffu, pA, off);
            pB += __shfl_xor_sync(0xffffffffu, pB, off);
        }
        upd(pA, sA, accA, xlA);
        upd(pB, sB, accB, xlB);
    }

    float iA = 1.f / sA, iB = 1.f / sB;
    accA.x *= iA; accA.y *= iA; accA.z *= iA; accA.w *= iA;
    accB.x *= iB; accB.y *= iB; accB.z *= iB; accB.w *= iB;
    accA.x += __shfl_xor_sync(0xffffffffu, accA.x, 16);
    accA.y += __shfl_xor_sync(0xffffffffu, accA.y, 16);
    accA.z += __shfl_xor_sync(0xffffffffu, accA.z, 16);
    accA.w += __shfl_xor_sync(0xffffffffu, accA.w, 16);
    accB.x += __shfl_xor_sync(0xffffffffu, accB.x, 16);
    accB.y += __shfl_xor_sync(0xffffffffu, accB.y, 16);
    accB.z += __shfl_xor_sync(0xffffffffu, accB.z, 16);
    accB.w += __shfl_xor_sync(0xffffffffu, accB.w, 16);
    if (lane < 16) {
        float4 bv = *(const float4*)(bias + 4 * lane);
        float4 o;
        o.x = 0.25f * (accA.x + accB.x) + bv.x;
        o.y = 0.25f * (accA.y + accB.y) + bv.y;
        o.z = 0.25f * (accA.z + accB.z) + bv.z;
        o.w = 0.25f * (accA.w + accB.w) + bv.w;
        *(float4*)(out + (size_t)w * 64 + 4 * lane) = o;
    }
}

// ---------------- host ----------------
extern "C" void kernel_launch(void* const* d_in, const int* in_sizes, int n_in,
                              void* d_out, int out_size) {
    const float* x         = (const float*)d_in[0];
    const int* ei          = (const int*)d_in[1];
    const float* relations = (const float*)d_in[2];
    const int* relidx      = (const int*)d_in[3];
    const float* Wl[2]  = {(const float*)d_in[4],  (const float*)d_in[11]};
    const float* blv[2] = {(const float*)d_in[5],  (const float*)d_in[12]};
    const float* Wr[2]  = {(const float*)d_in[6],  (const float*)d_in[13]};
    const float* brv[2] = {(const float*)d_in[7],  (const float*)d_in[14]};
    const float* We[2]  = {(const float*)d_in[8],  (const float*)d_in[15]};
    const float* att[2] = {(const float*)d_in[9],  (const float*)d_in[16]};
    const float* bo[2]  = {(const float*)d_in[10], (const float*)d_in[17]};

    void *pxlh, *pxrh, *pre0, *pre1, *ph1, *pcnt;
    cudaGetSymbolAddress(&pxlh, g_xlh);
    cudaGetSymbolAddress(&pxrh, g_xrh);
    cudaGetSymbolAddress(&pre0, g_reh0);
    cudaGetSymbolAddress(&pre1, g_reh1);
    cudaGetSymbolAddress(&ph1, g_h1);
    cudaGetSymbolAddress(&pcnt, g_cnt);

    dim3 gtc((NN + 63) / 64, 4, 2);
    dim3 gr((RT + 127) / 128, 4);

    cudaStream_t s2;
    cudaStreamCreateWithFlags(&s2, cudaStreamNonBlocking);
    cudaEvent_t eFork, ePre, eB2;
    cudaEventCreateWithFlags(&eFork, cudaEventDisableTiming);
    cudaEventCreateWithFlags(&ePre, cudaEventDisableTiming);
    cudaEventCreateWithFlags(&eB2, cudaEventDisableTiming);

    cudaEventRecord(eFork, 0);
    cudaStreamWaitEvent(s2, eFork, 0);

    // --- branch B (s2): CSR build, then layer-1 re GEMM + relations copy ---
    cudaMemsetAsync(pcnt, 0, 2 * NN * sizeof(int), s2);
    k_count<<<(EE + 255) / 256, 256, 0, s2>>>(ei);
    k_scanA<<<SCAN_BLOCKS, 1024, 0, s2>>>();
    k_scanB<<<1, 32, 0, s2>>>();
    k_scanC<<<SCAN_BLOCKS, 1024, 0, s2>>>();
    k_scatter<<<(EE + 255) / 256, 256, 0, s2>>>(ei);
    k_sortpack<<<(NN * 32 + 255) / 256, 256, 0, s2>>>(ei, relidx);
    cudaEventRecord(ePre, s2);
    k_gemm_re<<<gr, 256, 0, s2>>>(relations, We[1], (__half2*)pre1, RT);
    if (out_size >= NN * 64 + RT * 64)
        cudaMemcpyAsync((float*)d_out + (size_t)NN * 64, relations,
                        (size_t)RT * 64 * sizeof(float), cudaMemcpyDeviceToDevice, s2);
    cudaEventRecord(eB2, s2);

    // --- branch A (main stream): layer-0 projections ---
    k_gemm_tc<<<gtc, 256>>>(x, Wl[0], blv[0], (__half2*)pxlh,
                            Wr[0], brv[0], (__half2*)pxrh, NN);
    k_gemm_re<<<gr, 256>>>(relations, We[0], (__half2*)pre0, RT);

    cudaStreamWaitEvent(0, ePre, 0);
    k_fused<<<(NN + 7) / 8, 256>>>(att[0], bo[0], (float*)ph1, (const __half2*)pre0);

    // layer 1
    k_gemm_tc<<<gtc, 256>>>((const float*)ph1, Wl[1], blv[1], (__half2*)pxlh,
                            Wr[1], brv[1], (__half2*)pxrh, NN);
    cudaStreamWaitEvent(0, eB2, 0);
    k_fused<<<(NN + 7) / 8, 256>>>(att[1], bo[1], (float*)d_out, (const __half2*)pre1);
}